// round 4
// baseline (speedup 1.0000x reference)
#include <cuda_runtime.h>

#define NN 50000
#define EE 1600000
#define ETOT (EE + NN)
#define C1 256
#define HIDV 64
#define SLOPE 0.2f

// ------------------------- scratch (static device globals) -------------------------
__device__ __align__(16) float g_hw[(size_t)NN * C1];     // GEMM output (hW)
__device__ __align__(16) float g_feat[(size_t)NN * C1];   // post-BN features
__device__ __align__(16) float g_agg[(size_t)NN * C1];    // attention aggregate
__device__ __align__(16) float g_h3[(size_t)NN * HIDV];   // layer-3 output
__device__ float g_ls[NN * 4];
__device__ float g_ld[NN * 4];
__device__ int   g_deg[NN];
__device__ int   g_off[NN + 1];
__device__ int   g_cur[NN];
__device__ int   g_csr[ETOT];
__device__ float g_bnsum[C1];
__device__ float g_bnsq[C1];
__device__ float g_mu[C1];
__device__ float g_rstd[C1];
__device__ float g_w2v[HIDV];
__device__ float g_cb;
__device__ float g_hs[NN];
__device__ float g_hd[NN];

// ------------------------- CSR build -------------------------
__global__ void k_init_deg() {
    int i = blockIdx.x * blockDim.x + threadIdx.x;
    if (i < NN) g_deg[i] = 1;   // self loop
}

__global__ void k_hist(const int* __restrict__ ei) {
    int e = blockIdx.x * blockDim.x + threadIdx.x;
    if (e < EE) {
        int d = ei[EE + e];
        atomicAdd(&g_deg[d], 1);
    }
}

__global__ void k_scan() {
    __shared__ int sh[1024];
    int t = threadIdx.x;
    int carry = 0;
    for (int base = 0; base < NN; base += 1024) {
        int i = base + t;
        int v = (i < NN) ? g_deg[i] : 0;
        sh[t] = v;
        __syncthreads();
        for (int st = 1; st < 1024; st <<= 1) {
            int add = (t >= st) ? sh[t - st] : 0;
            __syncthreads();
            sh[t] += add;
            __syncthreads();
        }
        if (i < NN) {
            int ex = carry + sh[t] - v;
            g_off[i] = ex;
            g_cur[i] = ex;
        }
        int tot = sh[1023];
        __syncthreads();
        carry += tot;
    }
    if (t == 0) g_off[NN] = carry;
}

__global__ void k_scatter(const int* __restrict__ ei) {
    int e = blockIdx.x * blockDim.x + threadIdx.x;
    if (e >= ETOT) return;
    int s, d;
    if (e < EE) { s = ei[e]; d = ei[EE + e]; }
    else        { s = e - EE; d = e - EE; }
    int pos = atomicAdd(&g_cur[d], 1);
    g_csr[pos] = s;
}

// ------------------------- SGEMM 128x128x8, fp32; writes g_hw -------------------------
// A_SRC: 0 = use Aparam (harness input), 1 = use g_feat
template <int A_SRC>
__global__ __launch_bounds__(256) void k_sgemm(const float* __restrict__ Aparam,
                                               const float* __restrict__ B,
                                               int M, int K, int Nc) {
    const float* A = (A_SRC == 0) ? Aparam : (const float*)g_feat;
    __shared__ float As[8][128];
    __shared__ float Bs[8][128];
    int t = threadIdx.x;
    int ty = t >> 4, tx = t & 15;
    int rowBase = blockIdx.y * 128;
    int colBase = blockIdx.x * 128;
    float acc[8][8];
#pragma unroll
    for (int i = 0; i < 8; i++)
#pragma unroll
        for (int j = 0; j < 8; j++) acc[i][j] = 0.f;

    for (int k0 = 0; k0 < K; k0 += 8) {
        {   // A tile: 128 rows x 8 k
            int lrow = t >> 1, lk = (t & 1) * 4;
            int grow = rowBase + lrow;
            float4 v = make_float4(0.f, 0.f, 0.f, 0.f);
            if (grow < M)
                v = *reinterpret_cast<const float4*>(A + (size_t)grow * K + k0 + lk);
            As[lk + 0][lrow] = v.x;
            As[lk + 1][lrow] = v.y;
            As[lk + 2][lrow] = v.z;
            As[lk + 3][lrow] = v.w;
        }
        {   // B tile: 8 k x 128 cols
            int lk = t >> 5, lcol = (t & 31) * 4;
            int gcol = colBase + lcol;
            float4 v = make_float4(0.f, 0.f, 0.f, 0.f);
            if (gcol < Nc)
                v = *reinterpret_cast<const float4*>(B + (size_t)(k0 + lk) * Nc + gcol);
            *reinterpret_cast<float4*>(&Bs[lk][lcol]) = v;
        }
        __syncthreads();
#pragma unroll
        for (int k = 0; k < 8; k++) {
            float a[8], b[8];
            *reinterpret_cast<float4*>(&a[0]) = *reinterpret_cast<float4*>(&As[k][ty * 8]);
            *reinterpret_cast<float4*>(&a[4]) = *reinterpret_cast<float4*>(&As[k][ty * 8 + 4]);
            *reinterpret_cast<float4*>(&b[0]) = *reinterpret_cast<float4*>(&Bs[k][tx * 8]);
            *reinterpret_cast<float4*>(&b[4]) = *reinterpret_cast<float4*>(&Bs[k][tx * 8 + 4]);
#pragma unroll
            for (int i = 0; i < 8; i++)
#pragma unroll
                for (int j = 0; j < 8; j++) acc[i][j] += a[i] * b[j];
        }
        __syncthreads();
    }
#pragma unroll
    for (int i = 0; i < 8; i++) {
        int row = rowBase + ty * 8 + i;
        if (row >= M) continue;
        int col = colBase + tx * 8;
        if (col < Nc)
            *reinterpret_cast<float4*>(g_hw + (size_t)row * Nc + col) =
                *reinterpret_cast<float4*>(&acc[i][0]);
        if (col + 4 < Nc)
            *reinterpret_cast<float4*>(g_hw + (size_t)row * Nc + col + 4) =
                *reinterpret_cast<float4*>(&acc[i][4]);
    }
}

// ------------------------- ls/ld (attention logits per node); reads g_hw --------------
// blockDim = C (256 or 64), one block per node
__global__ void k_lsld(const float* __restrict__ as, const float* __restrict__ ad, int C) {
    __shared__ float s1[256], s2[256];
    int n = blockIdx.x;
    int t = threadIdx.x;
    float v = g_hw[(size_t)n * C + t];
    s1[t] = v * as[t];
    s2[t] = v * ad[t];
    __syncthreads();
    for (int st = 32; st >= 1; st >>= 1) {
        if ((t & 63) < st) { s1[t] += s1[t + st]; s2[t] += s2[t + st]; }
        __syncthreads();
    }
    if ((t & 63) == 0) {
        int h = t >> 6;
        int H = C >> 6;
        g_ls[n * H + h] = s1[t];
        g_ld[n * H + h] = s2[t];
    }
}

// ------------------------- GAT aggregate: one warp per dst node; reads g_hw -----------
// DSTSEL: 0 -> g_agg, 1 -> g_h3
template <int H, int DSTSEL>
__global__ void k_aggregate(const float* __restrict__ bias) {
    const int C = H * 64;
    const int NACC = C / 32;
    float* out = (DSTSEL == 0) ? (float*)g_agg : (float*)g_h3;
    int w = (blockIdx.x * blockDim.x + threadIdx.x) >> 5;
    int lane = threadIdx.x & 31;
    if (w >= NN) return;
    int n = w;
    int beg = g_off[n], end = g_off[n + 1];

    float ldh[H];
#pragma unroll
    for (int h = 0; h < H; h++) ldh[h] = g_ld[n * H + h];

    // pass 1: segment max (lane-strided over edges)
    float m[H];
#pragma unroll
    for (int h = 0; h < H; h++) m[h] = -1e30f;
    for (int i = beg + lane; i < end; i += 32) {
        int s = g_csr[i];
#pragma unroll
        for (int h = 0; h < H; h++) {
            float lg = g_ls[s * H + h] + ldh[h];
            lg = lg > 0.f ? lg : SLOPE * lg;
            m[h] = fmaxf(m[h], lg);
        }
    }
#pragma unroll
    for (int h = 0; h < H; h++)
        for (int off = 16; off; off >>= 1)
            m[h] = fmaxf(m[h], __shfl_xor_sync(0xffffffffu, m[h], off));

    // pass 2: accumulate exp-sum and weighted features (edges sequential, warp cooperative)
    float ssum[H];
#pragma unroll
    for (int h = 0; h < H; h++) ssum[h] = 0.f;
    float acc[NACC];
#pragma unroll
    for (int j = 0; j < NACC; j++) acc[j] = 0.f;

    for (int i = beg; i < end; i++) {
        int s = g_csr[i];
        float p[H];
#pragma unroll
        for (int h = 0; h < H; h++) {
            float lg = g_ls[s * H + h] + ldh[h];
            lg = lg > 0.f ? lg : SLOPE * lg;
            p[h] = __expf(lg - m[h]);
            ssum[h] += p[h];
        }
        const float* hs = g_hw + (size_t)s * C;
#pragma unroll
        for (int j = 0; j < NACC; j++) {
            int c = lane + 32 * j;
            acc[j] += p[c >> 6] * hs[c];
        }
    }

    float inv[H];
#pragma unroll
    for (int h = 0; h < H; h++) inv[h] = 1.f / (ssum[h] + 1e-16f);
#pragma unroll
    for (int j = 0; j < NACC; j++) {
        int c = lane + 32 * j;
        out[(size_t)n * C + c] = acc[j] * inv[c >> 6] + bias[c];
    }
}

// ------------------------- ELU + BatchNorm (reads g_agg, writes g_feat) ---------------
__device__ __forceinline__ float eluf(float x) { return x > 0.f ? x : expm1f(x); }

__global__ void k_bn_zero() {
    int t = threadIdx.x;
    g_bnsum[t] = 0.f;
    g_bnsq[t] = 0.f;
}

__global__ void k_bn_stats() {
    int t = threadIdx.x;  // 256 = one column per thread
    float s = 0.f, s2 = 0.f;
    for (int r = blockIdx.x; r < NN; r += gridDim.x) {
        float v = eluf(g_agg[(size_t)r * C1 + t]);
        s += v;
        s2 += v * v;
    }
    atomicAdd(&g_bnsum[t], s);
    atomicAdd(&g_bnsq[t], s2);
}

__global__ void k_bn_finalize() {
    int t = threadIdx.x;
    float mu = g_bnsum[t] / (float)NN;
    float var = g_bnsq[t] / (float)NN - mu * mu;
    g_mu[t] = mu;
    g_rstd[t] = rsqrtf(var + 1e-5f);
}

__global__ void k_bn_apply(const float* __restrict__ gam, const float* __restrict__ bet) {
    size_t i = (size_t)blockIdx.x * blockDim.x + threadIdx.x;
    if (i >= (size_t)NN * C1) return;
    int c = (int)(i & (C1 - 1));
    float v = eluf(g_agg[i]);
    g_feat[i] = (v - g_mu[c]) * g_rstd[c] * gam[c] + bet[c];
}

// ------------------------- final scorer prep -------------------------
__global__ void k_prep_final(const float* __restrict__ mlpW2, const float* __restrict__ mlpb2,
                             const float* __restrict__ fcW, const float* __restrict__ fcb) {
    int j = threadIdx.x;  // 64
    float s = 0.f;
    for (int k = 0; k < 64; k++) s += mlpW2[j * 64 + k] * fcW[128 + k];
    g_w2v[j] = s;
    if (j == 0) {
        float c = fcb[0];
        for (int k = 0; k < 64; k++) c += mlpb2[k] * fcW[128 + k];
        g_cb = c;
    }
}

// per-node scalars hs = h3 . fcW[0:64], hd = h3 . fcW[64:128]; one warp per node
__global__ void k_node_scalars(const float* __restrict__ fcW) {
    int w = (blockIdx.x * blockDim.x + threadIdx.x) >> 5;
    int lane = threadIdx.x & 31;
    if (w >= NN) return;
    const float* h = g_h3 + (size_t)w * 64;
    float v0 = h[lane], v1 = h[lane + 32];
    float a = v0 * fcW[lane] + v1 * fcW[lane + 32];
    float b = v0 * fcW[64 + lane] + v1 * fcW[96 + lane];
    for (int off = 16; off; off >>= 1) {
        a += __shfl_xor_sync(0xffffffffu, a, off);
        b += __shfl_xor_sync(0xffffffffu, b, off);
    }
    if (lane == 0) { g_hs[w] = a; g_hd[w] = b; }
}

// per-edge output: folded edge-MLP + gathered node scalars
__global__ __launch_bounds__(256) void k_edge_out(const int* __restrict__ ei,
                                                  const float* __restrict__ ea,
                                                  const float* __restrict__ mlpW1,
                                                  const float* __restrict__ mlpb1,
                                                  float* __restrict__ outp) {
    __shared__ float w1s[16 * 64];
    __shared__ float b1s[64];
    __shared__ float w2vs[64];
    int t = threadIdx.x;
    for (int i = t; i < 16 * 64; i += 256) w1s[i] = mlpW1[i];
    if (t < 64) { b1s[t] = mlpb1[t]; w2vs[t] = g_w2v[t]; }
    __syncthreads();

    int e = blockIdx.x * blockDim.x + threadIdx.x;
    if (e >= EE) return;

    float r[16];
    const float4* pe = reinterpret_cast<const float4*>(ea + (size_t)e * 16);
#pragma unroll
    for (int q = 0; q < 4; q++) {
        float4 v = pe[q];
        r[q * 4 + 0] = v.x; r[q * 4 + 1] = v.y; r[q * 4 + 2] = v.z; r[q * 4 + 3] = v.w;
    }

    float dot = 0.f;
#pragma unroll 8
    for (int j = 0; j < 64; j++) {
        float acc = b1s[j];
#pragma unroll
        for (int k = 0; k < 16; k++) acc += r[k] * w1s[k * 64 + j];
        dot += fmaxf(acc, 0.f) * w2vs[j];
    }
    int s = ei[e];
    int d = ei[EE + e];
    outp[e] = g_hs[s] + g_hd[d] + dot + g_cb;
}

// ------------------------- launch -------------------------
static inline dim3 gemm_grid(int M, int Nc) { return dim3((Nc + 127) / 128, (M + 127) / 128); }

extern "C" void kernel_launch(void* const* d_in, const int* in_sizes, int n_in,
                              void* d_out, int out_size) {
    const float* x     = (const float*)d_in[0];
    const int*   ei    = (const int*)d_in[1];     // int64 in reference -> int32 from harness
    const float* ea    = (const float*)d_in[2];
    const float* W1    = (const float*)d_in[3];
    const float* a1s   = (const float*)d_in[4];
    const float* a1d   = (const float*)d_in[5];
    const float* b1    = (const float*)d_in[6];
    const float* W2    = (const float*)d_in[7];
    const float* a2s   = (const float*)d_in[8];
    const float* a2d   = (const float*)d_in[9];
    const float* b2    = (const float*)d_in[10];
    const float* W3    = (const float*)d_in[11];
    const float* a3s   = (const float*)d_in[12];
    const float* a3d   = (const float*)d_in[13];
    const float* b3    = (const float*)d_in[14];
    const float* bn1g  = (const float*)d_in[15];
    const float* bn1b  = (const float*)d_in[16];
    const float* bn2g  = (const float*)d_in[17];
    const float* bn2b  = (const float*)d_in[18];
    const float* mlpW1 = (const float*)d_in[19];
    const float* mlpb1 = (const float*)d_in[20];
    const float* mlpW2 = (const float*)d_in[21];
    const float* mlpb2 = (const float*)d_in[22];
    const float* fcW   = (const float*)d_in[23];
    const float* fcb   = (const float*)d_in[24];
    float* outp = (float*)d_out;

    // CSR build (by dst, self-loops included)
    k_init_deg<<<(NN + 255) / 256, 256>>>();
    k_hist<<<(EE + 255) / 256, 256>>>(ei);
    k_scan<<<1, 1024>>>();
    k_scatter<<<(ETOT + 255) / 256, 256>>>(ei);

    const int aggBlocks = (NN * 32 + 255) / 256;
    const int bnApplyBlocks = (int)(((size_t)NN * C1 + 255) / 256);

    // ---- layer 1: x[50000,128] @ W1[128,256]
    k_sgemm<0><<<gemm_grid(NN, C1), 256>>>(x, W1, NN, 128, C1);
    k_lsld<<<NN, C1>>>(a1s, a1d, C1);
    k_aggregate<4, 0><<<aggBlocks, 256>>>(b1);
    k_bn_zero<<<1, C1>>>();
    k_bn_stats<<<512, C1>>>();
    k_bn_finalize<<<1, C1>>>();
    k_bn_apply<<<bnApplyBlocks, 256>>>(bn1g, bn1b);

    // ---- layer 2: g_feat @ W2[256,256]
    k_sgemm<1><<<gemm_grid(NN, C1), 256>>>(nullptr, W2, NN, C1, C1);
    k_lsld<<<NN, C1>>>(a2s, a2d, C1);
    k_aggregate<4, 0><<<aggBlocks, 256>>>(b2);
    k_bn_zero<<<1, C1>>>();
    k_bn_stats<<<512, C1>>>();
    k_bn_finalize<<<1, C1>>>();
    k_bn_apply<<<bnApplyBlocks, 256>>>(bn2g, bn2b);

    // ---- layer 3: g_feat @ W3[256,64], 1 head
    k_sgemm<1><<<gemm_grid(NN, HIDV), 256>>>(nullptr, W3, NN, C1, HIDV);
    k_lsld<<<NN, HIDV>>>(a3s, a3d, HIDV);
    k_aggregate<1, 1><<<aggBlocks, 256>>>(b3);

    // ---- final scorer
    k_prep_final<<<1, 64>>>(mlpW2, mlpb2, fcW, fcb);
    k_node_scalars<<<(NN * 32 + 255) / 256, 256>>>(fcW);
    k_edge_out<<<(EE + 255) / 256, 256>>>(ei, ea, mlpW1, mlpb1, outp);

    (void)in_sizes; (void)n_in; (void)out_size;
}

// round 5
// speedup vs baseline: 1.0711x; 1.0711x over previous
#include <cuda_runtime.h>

#define NN 50000
#define EE 1600000
#define ETOT (EE + NN)
#define C1 256
#define HIDV 64
#define SLOPE 0.2f

// ------------------------- scratch (static device globals) -------------------------
__device__ __align__(16) float g_hw[(size_t)NN * C1];     // GEMM output (hW)
__device__ __align__(16) float g_feat[(size_t)NN * C1];   // post-BN features
__device__ __align__(16) float g_agg[(size_t)NN * C1];    // attention aggregate
__device__ __align__(16) float g_h3[(size_t)NN * HIDV];   // layer-3 output
__device__ float g_ls[NN * 4];
__device__ float g_ld[NN * 4];
__device__ int   g_deg[NN];
__device__ int   g_off[NN + 1];
__device__ int   g_cur[NN];
__device__ int   g_csr[ETOT];
__device__ float g_bnsum[C1];
__device__ float g_bnsq[C1];
__device__ float g_mu[C1];
__device__ float g_rstd[C1];
__device__ float g_w2v[HIDV];
__device__ float g_cb;
__device__ float g_hs[NN];
__device__ float g_hd[NN];

// ------------------------- CSR build -------------------------
__global__ void k_init_deg() {
    int i = blockIdx.x * blockDim.x + threadIdx.x;
    if (i < NN) g_deg[i] = 1;   // self loop
}

__global__ void k_hist(const int* __restrict__ ei) {
    int e = blockIdx.x * blockDim.x + threadIdx.x;
    if (e < EE) {
        int d = ei[EE + e];
        atomicAdd(&g_deg[d], 1);
    }
}

__global__ void k_scan() {
    __shared__ int sh[1024];
    int t = threadIdx.x;
    int carry = 0;
    for (int base = 0; base < NN; base += 1024) {
        int i = base + t;
        int v = (i < NN) ? g_deg[i] : 0;
        sh[t] = v;
        __syncthreads();
        for (int st = 1; st < 1024; st <<= 1) {
            int add = (t >= st) ? sh[t - st] : 0;
            __syncthreads();
            sh[t] += add;
            __syncthreads();
        }
        if (i < NN) {
            int ex = carry + sh[t] - v;
            g_off[i] = ex;
            g_cur[i] = ex;
        }
        int tot = sh[1023];
        __syncthreads();
        carry += tot;
    }
    if (t == 0) g_off[NN] = carry;
}

__global__ void k_scatter(const int* __restrict__ ei) {
    int e = blockIdx.x * blockDim.x + threadIdx.x;
    if (e >= ETOT) return;
    int s, d;
    if (e < EE) { s = ei[e]; d = ei[EE + e]; }
    else        { s = e - EE; d = e - EE; }
    int pos = atomicAdd(&g_cur[d], 1);
    g_csr[pos] = s;
}

// ------------------------- TF32 split-precision tensor-core GEMM ----------------------
// C[M,Nc] = A[M,K] @ B[K,Nc], fp32 in/out, tf32 hi/lo split accumulation (fp32 quality).
// Block tile 128x128, K-chunk 32. 8 warps: 4 (M) x 2 (N); warp tile 32x64.
__device__ __forceinline__ void split_tf32(float x, unsigned& hi, unsigned& lo) {
    unsigned h;
    asm("cvt.rna.tf32.f32 %0, %1;" : "=r"(h) : "f"(x));
    float l = x - __uint_as_float(h);
    unsigned lb;
    asm("cvt.rna.tf32.f32 %0, %1;" : "=r"(lb) : "f"(l));
    hi = h; lo = lb;
}

__device__ __forceinline__ void mma_tf32(float* c, const unsigned* a, const unsigned* b) {
    asm volatile("mma.sync.aligned.m16n8k8.row.col.f32.tf32.tf32.f32 "
                 "{%0,%1,%2,%3}, {%4,%5,%6,%7}, {%8,%9}, {%0,%1,%2,%3};"
                 : "+f"(c[0]), "+f"(c[1]), "+f"(c[2]), "+f"(c[3])
                 : "r"(a[0]), "r"(a[1]), "r"(a[2]), "r"(a[3]),
                   "r"(b[0]), "r"(b[1]));
}

#define AS_STRIDE 36
#define BS_STRIDE 132

template <int A_SRC>
__global__ __launch_bounds__(256, 2) void k_gemm_tf32(const float* __restrict__ Aparam,
                                                      const float* __restrict__ B,
                                                      int M, int K, int Nc) {
    const float* A = (A_SRC == 0) ? Aparam : (const float*)g_feat;
    __shared__ float As[128][AS_STRIDE];   // [row][k]   (conflict-free frag loads)
    __shared__ float Bs[32][BS_STRIDE];    // [k][col]   (float4 STS, 2-way frag loads)

    int t = threadIdx.x;
    int lane = t & 31;
    int wid = t >> 5;
    int warpM = (wid & 3) * 32;
    int warpN = (wid >> 2) * 64;
    int rowBase = blockIdx.y * 128;
    int colBase = blockIdx.x * 128;

    float acc[2][8][4];
#pragma unroll
    for (int mt = 0; mt < 2; mt++)
#pragma unroll
        for (int nt = 0; nt < 8; nt++)
#pragma unroll
            for (int r = 0; r < 4; r++) acc[mt][nt][r] = 0.f;

    for (int k0 = 0; k0 < K; k0 += 32) {
        // ---- A tile 128x32 (row-major, stride K; K % 32 == 0)
#pragma unroll
        for (int i = 0; i < 4; i++) {
            int row = i * 32 + (t >> 3);
            int kk = (t & 7) * 4;
            float4 v = make_float4(0.f, 0.f, 0.f, 0.f);
            int gr = rowBase + row;
            if (gr < M)
                v = *reinterpret_cast<const float4*>(A + (size_t)gr * K + k0 + kk);
            As[row][kk + 0] = v.x;
            As[row][kk + 1] = v.y;
            As[row][kk + 2] = v.z;
            As[row][kk + 3] = v.w;
        }
        // ---- B tile 32x128 (row-major, stride Nc)
#pragma unroll
        for (int i = 0; i < 4; i++) {
            int kk = i * 8 + wid;
            int col = lane * 4;
            int gc = colBase + col;
            float4 v = make_float4(0.f, 0.f, 0.f, 0.f);
            if (gc + 3 < Nc) {
                v = *reinterpret_cast<const float4*>(B + (size_t)(k0 + kk) * Nc + gc);
            } else if (gc < Nc) {
                const float* bp = B + (size_t)(k0 + kk) * Nc;
                v.x = bp[gc];
                if (gc + 1 < Nc) v.y = bp[gc + 1];
                if (gc + 2 < Nc) v.z = bp[gc + 2];
            }
            *reinterpret_cast<float4*>(&Bs[kk][col]) = v;
        }
        __syncthreads();

#pragma unroll
        for (int ks = 0; ks < 32; ks += 8) {
            unsigned ahi[2][4], alo[2][4];
            int ar = warpM + (lane >> 2);
            int ak = ks + (lane & 3);
#pragma unroll
            for (int mt = 0; mt < 2; mt++) {
                float a0 = As[ar + mt * 16][ak];
                float a1 = As[ar + mt * 16 + 8][ak];
                float a2 = As[ar + mt * 16][ak + 4];
                float a3 = As[ar + mt * 16 + 8][ak + 4];
                split_tf32(a0, ahi[mt][0], alo[mt][0]);
                split_tf32(a1, ahi[mt][1], alo[mt][1]);
                split_tf32(a2, ahi[mt][2], alo[mt][2]);
                split_tf32(a3, ahi[mt][3], alo[mt][3]);
            }
#pragma unroll
            for (int nt = 0; nt < 8; nt++) {
                int bn = warpN + nt * 8 + (lane >> 2);
                int bk = ks + (lane & 3);
                float b0f = Bs[bk][bn];
                float b1f = Bs[bk + 4][bn];
                unsigned bhi[2], blo[2];
                split_tf32(b0f, bhi[0], blo[0]);
                split_tf32(b1f, bhi[1], blo[1]);
#pragma unroll
                for (int mt = 0; mt < 2; mt++) {
                    mma_tf32(acc[mt][nt], ahi[mt], bhi);
                    mma_tf32(acc[mt][nt], alo[mt], bhi);
                    mma_tf32(acc[mt][nt], ahi[mt], blo);
                }
            }
        }
        __syncthreads();
    }

    // ---- store
#pragma unroll
    for (int mt = 0; mt < 2; mt++) {
#pragma unroll
        for (int nt = 0; nt < 8; nt++) {
            int row0 = rowBase + warpM + mt * 16 + (lane >> 2);
            int col0 = colBase + warpN + nt * 8 + (lane & 3) * 2;
            if (col0 < Nc) {
                if (row0 < M)
                    *reinterpret_cast<float2*>(g_hw + (size_t)row0 * Nc + col0) =
                        make_float2(acc[mt][nt][0], acc[mt][nt][1]);
                if (row0 + 8 < M)
                    *reinterpret_cast<float2*>(g_hw + (size_t)(row0 + 8) * Nc + col0) =
                        make_float2(acc[mt][nt][2], acc[mt][nt][3]);
            }
        }
    }
}

// ------------------------- ls/ld (attention logits per node); reads g_hw --------------
__global__ void k_lsld(const float* __restrict__ as, const float* __restrict__ ad, int C) {
    __shared__ float s1[256], s2[256];
    int n = blockIdx.x;
    int t = threadIdx.x;
    float v = g_hw[(size_t)n * C + t];
    s1[t] = v * as[t];
    s2[t] = v * ad[t];
    __syncthreads();
    for (int st = 32; st >= 1; st >>= 1) {
        if ((t & 63) < st) { s1[t] += s1[t + st]; s2[t] += s2[t + st]; }
        __syncthreads();
    }
    if ((t & 63) == 0) {
        int h = t >> 6;
        int H = C >> 6;
        g_ls[n * H + h] = s1[t];
        g_ld[n * H + h] = s2[t];
    }
}

// ------------------------- GAT aggregate: one warp per dst node; reads g_hw -----------
template <int H, int DSTSEL>
__global__ void k_aggregate(const float* __restrict__ bias) {
    const int C = H * 64;
    const int NACC = C / 32;
    float* out = (DSTSEL == 0) ? (float*)g_agg : (float*)g_h3;
    int w = (blockIdx.x * blockDim.x + threadIdx.x) >> 5;
    int lane = threadIdx.x & 31;
    if (w >= NN) return;
    int n = w;
    int beg = g_off[n], end = g_off[n + 1];

    float ldh[H];
#pragma unroll
    for (int h = 0; h < H; h++) ldh[h] = g_ld[n * H + h];

    float m[H];
#pragma unroll
    for (int h = 0; h < H; h++) m[h] = -1e30f;
    for (int i = beg + lane; i < end; i += 32) {
        int s = g_csr[i];
#pragma unroll
        for (int h = 0; h < H; h++) {
            float lg = g_ls[s * H + h] + ldh[h];
            lg = lg > 0.f ? lg : SLOPE * lg;
            m[h] = fmaxf(m[h], lg);
        }
    }
#pragma unroll
    for (int h = 0; h < H; h++)
        for (int off = 16; off; off >>= 1)
            m[h] = fmaxf(m[h], __shfl_xor_sync(0xffffffffu, m[h], off));

    float ssum[H];
#pragma unroll
    for (int h = 0; h < H; h++) ssum[h] = 0.f;
    float acc[NACC];
#pragma unroll
    for (int j = 0; j < NACC; j++) acc[j] = 0.f;

    for (int i = beg; i < end; i++) {
        int s = g_csr[i];
        float p[H];
#pragma unroll
        for (int h = 0; h < H; h++) {
            float lg = g_ls[s * H + h] + ldh[h];
            lg = lg > 0.f ? lg : SLOPE * lg;
            p[h] = __expf(lg - m[h]);
            ssum[h] += p[h];
        }
        const float* hs = g_hw + (size_t)s * C;
#pragma unroll
        for (int j = 0; j < NACC; j++) {
            int c = lane + 32 * j;
            acc[j] += p[c >> 6] * hs[c];
        }
    }

    float inv[H];
#pragma unroll
    for (int h = 0; h < H; h++) inv[h] = 1.f / (ssum[h] + 1e-16f);
#pragma unroll
    for (int j = 0; j < NACC; j++) {
        int c = lane + 32 * j;
        out[(size_t)n * C + c] = acc[j] * inv[c >> 6] + bias[c];
    }
}

// ------------------------- ELU + BatchNorm (reads g_agg, writes g_feat) ---------------
__device__ __forceinline__ float eluf(float x) { return x > 0.f ? x : expm1f(x); }

__global__ void k_bn_zero() {
    int t = threadIdx.x;
    g_bnsum[t] = 0.f;
    g_bnsq[t] = 0.f;
}

__global__ void k_bn_stats() {
    int t = threadIdx.x;
    float s = 0.f, s2 = 0.f;
    for (int r = blockIdx.x; r < NN; r += gridDim.x) {
        float v = eluf(g_agg[(size_t)r * C1 + t]);
        s += v;
        s2 += v * v;
    }
    atomicAdd(&g_bnsum[t], s);
    atomicAdd(&g_bnsq[t], s2);
}

__global__ void k_bn_finalize() {
    int t = threadIdx.x;
    float mu = g_bnsum[t] / (float)NN;
    float var = g_bnsq[t] / (float)NN - mu * mu;
    g_mu[t] = mu;
    g_rstd[t] = rsqrtf(var + 1e-5f);
}

__global__ void k_bn_apply(const float* __restrict__ gam, const float* __restrict__ bet) {
    size_t i = (size_t)blockIdx.x * blockDim.x + threadIdx.x;
    if (i >= (size_t)NN * C1) return;
    int c = (int)(i & (C1 - 1));
    float v = eluf(g_agg[i]);
    g_feat[i] = (v - g_mu[c]) * g_rstd[c] * gam[c] + bet[c];
}

// ------------------------- final scorer -------------------------
__global__ void k_prep_final(const float* __restrict__ mlpW2, const float* __restrict__ mlpb2,
                             const float* __restrict__ fcW, const float* __restrict__ fcb) {
    int j = threadIdx.x;
    float s = 0.f;
    for (int k = 0; k < 64; k++) s += mlpW2[j * 64 + k] * fcW[128 + k];
    g_w2v[j] = s;
    if (j == 0) {
        float c = fcb[0];
        for (int k = 0; k < 64; k++) c += mlpb2[k] * fcW[128 + k];
        g_cb = c;
    }
}

__global__ void k_node_scalars(const float* __restrict__ fcW) {
    int w = (blockIdx.x * blockDim.x + threadIdx.x) >> 5;
    int lane = threadIdx.x & 31;
    if (w >= NN) return;
    const float* h = g_h3 + (size_t)w * 64;
    float v0 = h[lane], v1 = h[lane + 32];
    float a = v0 * fcW[lane] + v1 * fcW[lane + 32];
    float b = v0 * fcW[64 + lane] + v1 * fcW[96 + lane];
    for (int off = 16; off; off >>= 1) {
        a += __shfl_xor_sync(0xffffffffu, a, off);
        b += __shfl_xor_sync(0xffffffffu, b, off);
    }
    if (lane == 0) { g_hs[w] = a; g_hd[w] = b; }
}

__global__ __launch_bounds__(256) void k_edge_out(const int* __restrict__ ei,
                                                  const float* __restrict__ ea,
                                                  const float* __restrict__ mlpW1,
                                                  const float* __restrict__ mlpb1,
                                                  float* __restrict__ outp) {
    __shared__ float w1s[16 * 64];
    __shared__ float b1s[64];
    __shared__ float w2vs[64];
    int t = threadIdx.x;
    for (int i = t; i < 16 * 64; i += 256) w1s[i] = mlpW1[i];
    if (t < 64) { b1s[t] = mlpb1[t]; w2vs[t] = g_w2v[t]; }
    __syncthreads();

    int e = blockIdx.x * blockDim.x + threadIdx.x;
    if (e >= EE) return;

    float r[16];
    const float4* pe = reinterpret_cast<const float4*>(ea + (size_t)e * 16);
#pragma unroll
    for (int q = 0; q < 4; q++) {
        float4 v = pe[q];
        r[q * 4 + 0] = v.x; r[q * 4 + 1] = v.y; r[q * 4 + 2] = v.z; r[q * 4 + 3] = v.w;
    }

    float dot = 0.f;
#pragma unroll 8
    for (int j = 0; j < 64; j++) {
        float acc = b1s[j];
#pragma unroll
        for (int k = 0; k < 16; k++) acc += r[k] * w1s[k * 64 + j];
        dot += fmaxf(acc, 0.f) * w2vs[j];
    }
    int s = ei[e];
    int d = ei[EE + e];
    outp[e] = g_hs[s] + g_hd[d] + dot + g_cb;
}

// ------------------------- launch -------------------------
static inline dim3 gemm_grid(int M, int Nc) { return dim3((Nc + 127) / 128, (M + 127) / 128); }

extern "C" void kernel_launch(void* const* d_in, const int* in_sizes, int n_in,
                              void* d_out, int out_size) {
    const float* x     = (const float*)d_in[0];
    const int*   ei    = (const int*)d_in[1];
    const float* ea    = (const float*)d_in[2];
    const float* W1    = (const float*)d_in[3];
    const float* a1s   = (const float*)d_in[4];
    const float* a1d   = (const float*)d_in[5];
    const float* b1    = (const float*)d_in[6];
    const float* W2    = (const float*)d_in[7];
    const float* a2s   = (const float*)d_in[8];
    const float* a2d   = (const float*)d_in[9];
    const float* b2    = (const float*)d_in[10];
    const float* W3    = (const float*)d_in[11];
    const float* a3s   = (const float*)d_in[12];
    const float* a3d   = (const float*)d_in[13];
    const float* b3    = (const float*)d_in[14];
    const float* bn1g  = (const float*)d_in[15];
    const float* bn1b  = (const float*)d_in[16];
    const float* bn2g  = (const float*)d_in[17];
    const float* bn2b  = (const float*)d_in[18];
    const float* mlpW1 = (const float*)d_in[19];
    const float* mlpb1 = (const float*)d_in[20];
    const float* mlpW2 = (const float*)d_in[21];
    const float* mlpb2 = (const float*)d_in[22];
    const float* fcW   = (const float*)d_in[23];
    const float* fcb   = (const float*)d_in[24];
    float* outp = (float*)d_out;

    // CSR build (by dst, self-loops included)
    k_init_deg<<<(NN + 255) / 256, 256>>>();
    k_hist<<<(EE + 255) / 256, 256>>>(ei);
    k_scan<<<1, 1024>>>();
    k_scatter<<<(ETOT + 255) / 256, 256>>>(ei);

    const int aggBlocks = (NN * 32 + 255) / 256;
    const int bnApplyBlocks = (int)(((size_t)NN * C1 + 255) / 256);

    // ---- layer 1: x[50000,128] @ W1[128,256]
    k_gemm_tf32<0><<<gemm_grid(NN, C1), 256>>>(x, W1, NN, 128, C1);
    k_lsld<<<NN, C1>>>(a1s, a1d, C1);
    k_aggregate<4, 0><<<aggBlocks, 256>>>(b1);
    k_bn_zero<<<1, C1>>>();
    k_bn_stats<<<512, C1>>>();
    k_bn_finalize<<<1, C1>>>();
    k_bn_apply<<<bnApplyBlocks, 256>>>(bn1g, bn1b);

    // ---- layer 2: g_feat @ W2[256,256]
    k_gemm_tf32<1><<<gemm_grid(NN, C1), 256>>>(nullptr, W2, NN, C1, C1);
    k_lsld<<<NN, C1>>>(a2s, a2d, C1);
    k_aggregate<4, 0><<<aggBlocks, 256>>>(b2);
    k_bn_zero<<<1, C1>>>();
    k_bn_stats<<<512, C1>>>();
    k_bn_finalize<<<1, C1>>>();
    k_bn_apply<<<bnApplyBlocks, 256>>>(bn2g, bn2b);

    // ---- layer 3: g_feat @ W3[256,64], 1 head
    k_gemm_tf32<1><<<gemm_grid(NN, HIDV), 256>>>(nullptr, W3, NN, C1, HIDV);
    k_lsld<<<NN, HIDV>>>(a3s, a3d, HIDV);
    k_aggregate<1, 1><<<aggBlocks, 256>>>(b3);

    // ---- final scorer
    k_prep_final<<<1, 64>>>(mlpW2, mlpb2, fcW, fcb);
    k_node_scalars<<<(NN * 32 + 255) / 256, 256>>>(fcW);
    k_edge_out<<<(EE + 255) / 256, 256>>>(ei, ea, mlpW1, mlpb1, outp);

    (void)in_sizes; (void)n_in; (void)out_size;
}

// round 6
// speedup vs baseline: 1.1996x; 1.1200x over previous
#include <cuda_runtime.h>

#define NN 50000
#define EE 1600000
#define ETOT (EE + NN)
#define C1 256
#define HIDV 64
#define SLOPE 0.2f

// ------------------------- scratch (static device globals) -------------------------
__device__ __align__(16) float g_hw[(size_t)NN * C1];     // GEMM output (hW)
__device__ __align__(16) float g_feat[(size_t)NN * C1];   // post-BN features
__device__ __align__(16) float g_agg[(size_t)NN * C1];    // attention aggregate
__device__ __align__(16) float g_h3[(size_t)NN * HIDV];   // layer-3 output
__device__ __align__(16) float g_ls[NN * 4];
__device__ __align__(16) float g_ld[NN * 4];
__device__ int   g_deg[NN];
__device__ int   g_off[NN + 1];
__device__ int   g_cur[NN];
__device__ int   g_csr[ETOT];
__device__ int   g_bsum[256];
__device__ float g_bnsum[C1];
__device__ float g_bnsq[C1];
__device__ float g_mu[C1];
__device__ float g_rstd[C1];
__device__ float g_w2v[HIDV];
__device__ float g_cb;
__device__ float g_hs[NN];
__device__ float g_hd[NN];
// pre-split tf32 weights (hi/lo). Offsets: W1@0 (32768), W2@32768 (65536), W3@98304 (16384)
__device__ __align__(16) unsigned g_whi[114688];
__device__ __align__(16) unsigned g_wlo[114688];

// ------------------------- tf32 helpers -------------------------
__device__ __forceinline__ void split_tf32(float x, unsigned& hi, unsigned& lo) {
    unsigned h;
    asm("cvt.rna.tf32.f32 %0, %1;" : "=r"(h) : "f"(x));
    float l = x - __uint_as_float(h);
    unsigned lb;
    asm("cvt.rna.tf32.f32 %0, %1;" : "=r"(lb) : "f"(l));
    hi = h; lo = lb;
}

__device__ __forceinline__ void mma_tf32(float* c, const unsigned* a, const unsigned* b) {
    asm volatile("mma.sync.aligned.m16n8k8.row.col.f32.tf32.tf32.f32 "
                 "{%0,%1,%2,%3}, {%4,%5,%6,%7}, {%8,%9}, {%0,%1,%2,%3};"
                 : "+f"(c[0]), "+f"(c[1]), "+f"(c[2]), "+f"(c[3])
                 : "r"(a[0]), "r"(a[1]), "r"(a[2]), "r"(a[3]),
                   "r"(b[0]), "r"(b[1]));
}

// ------------------------- weight pre-split -------------------------
__global__ void k_wsplit(const float* __restrict__ W, int count, int offset) {
    int i = blockIdx.x * blockDim.x + threadIdx.x;
    if (i < count) {
        unsigned h, l;
        split_tf32(W[i], h, l);
        g_whi[offset + i] = h;
        g_wlo[offset + i] = l;
    }
}

// ------------------------- CSR build -------------------------
__global__ void k_init_deg() {
    int i = blockIdx.x * blockDim.x + threadIdx.x;
    if (i < NN) g_deg[i] = 1;   // self loop
}

__global__ void k_hist(const int* __restrict__ ei) {
    int e = blockIdx.x * blockDim.x + threadIdx.x;
    if (e < EE) atomicAdd(&g_deg[ei[EE + e]], 1);
}

// two-level scan: 196 blocks x 256
__global__ void k_scan1() {
    __shared__ int sh[256];
    int t = threadIdx.x;
    int i = blockIdx.x * 256 + t;
    int v = (i < NN) ? g_deg[i] : 0;
    sh[t] = v;
    __syncthreads();
#pragma unroll
    for (int st = 1; st < 256; st <<= 1) {
        int a = (t >= st) ? sh[t - st] : 0;
        __syncthreads();
        sh[t] += a;
        __syncthreads();
    }
    if (i < NN) g_off[i] = sh[t] - v;         // block-local exclusive
    if (t == 255) g_bsum[blockIdx.x] = sh[255];
}

__global__ void k_scan2() {   // 1 block x 256; 196 block sums
    __shared__ int sh[256];
    int t = threadIdx.x;
    int v = (t < 196) ? g_bsum[t] : 0;
    sh[t] = v;
    __syncthreads();
#pragma unroll
    for (int st = 1; st < 256; st <<= 1) {
        int a = (t >= st) ? sh[t - st] : 0;
        __syncthreads();
        sh[t] += a;
        __syncthreads();
    }
    g_bsum[t] = sh[t] - v;                    // exclusive block offsets
    if (t == 255) g_off[NN] = sh[255];        // total
}

__global__ void k_scan3() {
    int i = blockIdx.x * blockDim.x + threadIdx.x;
    if (i < NN) {
        int o = g_off[i] + g_bsum[i >> 8];
        g_off[i] = o;
        g_cur[i] = o;
    }
}

__global__ void k_scatter(const int* __restrict__ ei) {
    int e = blockIdx.x * blockDim.x + threadIdx.x;
    if (e >= ETOT) return;
    int s, d;
    if (e < EE) { s = ei[e]; d = ei[EE + e]; }
    else        { s = e - EE; d = e - EE; }
    int pos = atomicAdd(&g_cur[d], 1);
    g_csr[pos] = s;
}

// ------------------------- TF32 split GEMM, pre-split B, k-chunk 16 -------------------
// C[M,Nc] = A[M,K] @ B[K,Nc]; B given as hi/lo tf32 at g_whi/g_wlo + boff.
// Block tile 128x128; 8 warps 4(M)x2(N), warp tile 32x64.
#define AS_STR 20
#define BS_STR 136

template <int A_SRC>
__global__ __launch_bounds__(256, 2) void k_gemm_tf32(const float* __restrict__ Aparam,
                                                      int boff, int M, int K, int Nc) {
    const float* A = (A_SRC == 0) ? Aparam : (const float*)g_feat;
    __shared__ float    As[128][AS_STR];
    __shared__ unsigned Bh[16][BS_STR];
    __shared__ unsigned Bl[16][BS_STR];

    int t = threadIdx.x;
    int lane = t & 31;
    int wid = t >> 5;
    int warpM = (wid & 3) * 32;
    int warpN = (wid >> 2) * 64;
    int rowBase = blockIdx.y * 128;
    int colBase = blockIdx.x * 128;

    float acc[2][8][4];
#pragma unroll
    for (int mt = 0; mt < 2; mt++)
#pragma unroll
        for (int nt = 0; nt < 8; nt++)
#pragma unroll
            for (int r = 0; r < 4; r++) acc[mt][nt][r] = 0.f;

    for (int k0 = 0; k0 < K; k0 += 16) {
        // A tile 128x16 (float4)
#pragma unroll
        for (int q = 0; q < 2; q++) {
            int i = t + 256 * q;
            int row = i >> 2, kk = (i & 3) * 4;
            int gr = rowBase + row;
            float4 v = make_float4(0.f, 0.f, 0.f, 0.f);
            if (gr < M)
                v = *reinterpret_cast<const float4*>(A + (size_t)gr * K + k0 + kk);
            *reinterpret_cast<float4*>(&As[row][kk]) = v;
        }
        // B hi/lo tiles 16x128 (uint4)
#pragma unroll
        for (int q = 0; q < 2; q++) {
            int i = t + 256 * q;
            int kk = i >> 5, c4 = (i & 31) * 4;
            int gc = colBase + c4;
            uint4 vh = make_uint4(0u, 0u, 0u, 0u);
            uint4 vl = make_uint4(0u, 0u, 0u, 0u);
            if (gc + 3 < Nc) {
                size_t idx = (size_t)boff + (size_t)(k0 + kk) * Nc + gc;
                vh = *reinterpret_cast<const uint4*>(g_whi + idx);
                vl = *reinterpret_cast<const uint4*>(g_wlo + idx);
            }
            *reinterpret_cast<uint4*>(&Bh[kk][c4]) = vh;
            *reinterpret_cast<uint4*>(&Bl[kk][c4]) = vl;
        }
        __syncthreads();

#pragma unroll
        for (int ks = 0; ks < 16; ks += 8) {
            unsigned ahi[2][4], alo[2][4];
            int ar = warpM + (lane >> 2);
            int ak = ks + (lane & 3);
#pragma unroll
            for (int mt = 0; mt < 2; mt++) {
                split_tf32(As[ar + mt * 16][ak],      ahi[mt][0], alo[mt][0]);
                split_tf32(As[ar + mt * 16 + 8][ak],  ahi[mt][1], alo[mt][1]);
                split_tf32(As[ar + mt * 16][ak + 4],  ahi[mt][2], alo[mt][2]);
                split_tf32(As[ar + mt * 16 + 8][ak + 4], ahi[mt][3], alo[mt][3]);
            }
            int bk = ks + (lane & 3);
#pragma unroll
            for (int nt = 0; nt < 8; nt++) {
                int bn = warpN + nt * 8 + (lane >> 2);
                unsigned bhi[2], blo[2];
                bhi[0] = Bh[bk][bn];     bhi[1] = Bh[bk + 4][bn];
                blo[0] = Bl[bk][bn];     blo[1] = Bl[bk + 4][bn];
#pragma unroll
                for (int mt = 0; mt < 2; mt++) {
                    mma_tf32(acc[mt][nt], ahi[mt], bhi);
                    mma_tf32(acc[mt][nt], alo[mt], bhi);
                    mma_tf32(acc[mt][nt], ahi[mt], blo);
                }
            }
        }
        __syncthreads();
    }

#pragma unroll
    for (int mt = 0; mt < 2; mt++) {
#pragma unroll
        for (int nt = 0; nt < 8; nt++) {
            int row0 = rowBase + warpM + mt * 16 + (lane >> 2);
            int col0 = colBase + warpN + nt * 8 + (lane & 3) * 2;
            if (col0 < Nc) {
                if (row0 < M)
                    *reinterpret_cast<float2*>(g_hw + (size_t)row0 * Nc + col0) =
                        make_float2(acc[mt][nt][0], acc[mt][nt][1]);
                if (row0 + 8 < M)
                    *reinterpret_cast<float2*>(g_hw + (size_t)(row0 + 8) * Nc + col0) =
                        make_float2(acc[mt][nt][2], acc[mt][nt][3]);
            }
        }
    }
}

// ------------------------- ls/ld (attention logits per node); reads g_hw --------------
__global__ void k_lsld(const float* __restrict__ as, const float* __restrict__ ad, int C) {
    __shared__ float s1[256], s2[256];
    int n = blockIdx.x;
    int t = threadIdx.x;
    float v = g_hw[(size_t)n * C + t];
    s1[t] = v * as[t];
    s2[t] = v * ad[t];
    __syncthreads();
    for (int st = 32; st >= 1; st >>= 1) {
        if ((t & 63) < st) { s1[t] += s1[t + st]; s2[t] += s2[t + st]; }
        __syncthreads();
    }
    if ((t & 63) == 0) {
        int h = t >> 6;
        int H = C >> 6;
        g_ls[n * H + h] = s1[t];
        g_ld[n * H + h] = s2[t];
    }
}

// ------------------------- GAT aggregate: one warp per dst; single-pass softmax -------
// Logits are bounded (|lg| < ~15), so exp without max-subtraction is safe and
// mathematically identical to the reference's max-shifted segment softmax.
template <int H, int DSTSEL>
__global__ void k_aggregate(const float* __restrict__ bias) {
    const int C = H * 64;
    float* out = (DSTSEL == 0) ? (float*)g_agg : (float*)g_h3;
    int w = (blockIdx.x * blockDim.x + threadIdx.x) >> 5;
    int lane = threadIdx.x & 31;
    if (w >= NN) return;
    int beg = g_off[w], end = g_off[w + 1];

    if (H == 4) {
        float4 ldv = *reinterpret_cast<const float4*>(g_ld + w * 4);
        float s0 = 0.f, s1 = 0.f, s2 = 0.f, s3 = 0.f;
        float4 acc0 = make_float4(0.f, 0.f, 0.f, 0.f);
        float4 acc1 = make_float4(0.f, 0.f, 0.f, 0.f);
        for (int i = beg; i < end; i++) {
            int s = g_csr[i];
            float4 lsv = *reinterpret_cast<const float4*>(g_ls + s * 4);
            float l0 = lsv.x + ldv.x; l0 = l0 > 0.f ? l0 : SLOPE * l0;
            float l1 = lsv.y + ldv.y; l1 = l1 > 0.f ? l1 : SLOPE * l1;
            float l2 = lsv.z + ldv.z; l2 = l2 > 0.f ? l2 : SLOPE * l2;
            float l3 = lsv.w + ldv.w; l3 = l3 > 0.f ? l3 : SLOPE * l3;
            float p0 = __expf(l0), p1 = __expf(l1), p2 = __expf(l2), p3 = __expf(l3);
            s0 += p0; s1 += p1; s2 += p2; s3 += p3;
            float pa = (lane & 16) ? p1 : p0;
            float pb = (lane & 16) ? p3 : p2;
            const float4* hs = reinterpret_cast<const float4*>(g_hw + (size_t)s * 256);
            float4 v0 = hs[lane];
            float4 v1 = hs[lane + 32];
            acc0.x += pa * v0.x; acc0.y += pa * v0.y; acc0.z += pa * v0.z; acc0.w += pa * v0.w;
            acc1.x += pb * v1.x; acc1.y += pb * v1.y; acc1.z += pb * v1.z; acc1.w += pb * v1.w;
        }
        float i0 = 1.f / (s0 + 1e-16f), i1 = 1.f / (s1 + 1e-16f);
        float i2 = 1.f / (s2 + 1e-16f), i3 = 1.f / (s3 + 1e-16f);
        float ia = (lane & 16) ? i1 : i0;
        float ib = (lane & 16) ? i3 : i2;
        const float4* bv = reinterpret_cast<const float4*>(bias);
        float4 b0 = bv[lane], b1 = bv[lane + 32];
        float4 o0 = make_float4(acc0.x * ia + b0.x, acc0.y * ia + b0.y,
                                acc0.z * ia + b0.z, acc0.w * ia + b0.w);
        float4 o1 = make_float4(acc1.x * ib + b1.x, acc1.y * ib + b1.y,
                                acc1.z * ib + b1.z, acc1.w * ib + b1.w);
        float4* op = reinterpret_cast<float4*>(out + (size_t)w * 256);
        op[lane] = o0;
        op[lane + 32] = o1;
    } else {
        float ldh = g_ld[w];
        float ssum = 0.f;
        float2 acc = make_float2(0.f, 0.f);
        for (int i = beg; i < end; i++) {
            int s = g_csr[i];
            float lg = g_ls[s] + ldh;
            lg = lg > 0.f ? lg : SLOPE * lg;
            float p = __expf(lg);
            ssum += p;
            float2 v = reinterpret_cast<const float2*>(g_hw + (size_t)s * 64)[lane];
            acc.x += p * v.x; acc.y += p * v.y;
        }
        float inv = 1.f / (ssum + 1e-16f);
        float2 b = reinterpret_cast<const float2*>(bias)[lane];
        reinterpret_cast<float2*>(out + (size_t)w * 64)[lane] =
            make_float2(acc.x * inv + b.x, acc.y * inv + b.y);
    }
}

// ------------------------- ELU + BatchNorm (reads g_agg, writes g_feat) ---------------
__device__ __forceinline__ float eluf(float x) { return x > 0.f ? x : expm1f(x); }

__global__ void k_bn_zero() {
    int t = threadIdx.x;
    g_bnsum[t] = 0.f;
    g_bnsq[t] = 0.f;
}

__global__ void k_bn_stats() {
    int t = threadIdx.x;
    float s = 0.f, s2 = 0.f;
    for (int r = blockIdx.x; r < NN; r += gridDim.x) {
        float v = eluf(g_agg[(size_t)r * C1 + t]);
        s += v;
        s2 += v * v;
    }
    atomicAdd(&g_bnsum[t], s);
    atomicAdd(&g_bnsq[t], s2);
}

__global__ void k_bn_finalize() {
    int t = threadIdx.x;
    float mu = g_bnsum[t] / (float)NN;
    float var = g_bnsq[t] / (float)NN - mu * mu;
    g_mu[t] = mu;
    g_rstd[t] = rsqrtf(var + 1e-5f);
}

__global__ void k_bn_apply(const float* __restrict__ gam, const float* __restrict__ bet) {
    size_t i = (size_t)blockIdx.x * blockDim.x + threadIdx.x;
    if (i >= (size_t)NN * C1) return;
    int c = (int)(i & (C1 - 1));
    float v = eluf(g_agg[i]);
    g_feat[i] = (v - g_mu[c]) * g_rstd[c] * gam[c] + bet[c];
}

// ------------------------- final scorer -------------------------
__global__ void k_prep_final(const float* __restrict__ mlpW2, const float* __restrict__ mlpb2,
                             const float* __restrict__ fcW, const float* __restrict__ fcb) {
    int j = threadIdx.x;
    float s = 0.f;
    for (int k = 0; k < 64; k++) s += mlpW2[j * 64 + k] * fcW[128 + k];
    g_w2v[j] = s;
    if (j == 0) {
        float c = fcb[0];
        for (int k = 0; k < 64; k++) c += mlpb2[k] * fcW[128 + k];
        g_cb = c;
    }
}

__global__ void k_node_scalars(const float* __restrict__ fcW) {
    int w = (blockIdx.x * blockDim.x + threadIdx.x) >> 5;
    int lane = threadIdx.x & 31;
    if (w >= NN) return;
    const float* h = g_h3 + (size_t)w * 64;
    float v0 = h[lane], v1 = h[lane + 32];
    float a = v0 * fcW[lane] + v1 * fcW[lane + 32];
    float b = v0 * fcW[64 + lane] + v1 * fcW[96 + lane];
    for (int off = 16; off; off >>= 1) {
        a += __shfl_xor_sync(0xffffffffu, a, off);
        b += __shfl_xor_sync(0xffffffffu, b, off);
    }
    if (lane == 0) { g_hs[w] = a; g_hd[w] = b; }
}

__global__ __launch_bounds__(256) void k_edge_out(const int* __restrict__ ei,
                                                  const float* __restrict__ ea,
                                                  const float* __restrict__ mlpW1,
                                                  const float* __restrict__ mlpb1,
                                                  float* __restrict__ outp) {
    __shared__ float w1s[16 * 64];
    __shared__ float b1s[64];
    __shared__ float w2vs[64];
    int t = threadIdx.x;
    for (int i = t; i < 16 * 64; i += 256) w1s[i] = mlpW1[i];
    if (t < 64) { b1s[t] = mlpb1[t]; w2vs[t] = g_w2v[t]; }
    __syncthreads();

    int e = blockIdx.x * blockDim.x + threadIdx.x;
    if (e >= EE) return;

    float r[16];
    const float4* pe = reinterpret_cast<const float4*>(ea + (size_t)e * 16);
#pragma unroll
    for (int q = 0; q < 4; q++) {
        float4 v = pe[q];
        r[q * 4 + 0] = v.x; r[q * 4 + 1] = v.y; r[q * 4 + 2] = v.z; r[q * 4 + 3] = v.w;
    }

    float dot = 0.f;
#pragma unroll 8
    for (int j = 0; j < 64; j++) {
        float acc = b1s[j];
#pragma unroll
        for (int k = 0; k < 16; k++) acc += r[k] * w1s[k * 64 + j];
        dot += fmaxf(acc, 0.f) * w2vs[j];
    }
    int s = ei[e];
    int d = ei[EE + e];
    outp[e] = g_hs[s] + g_hd[d] + dot + g_cb;
}

// ------------------------- launch -------------------------
static inline dim3 gemm_grid(int M, int Nc) { return dim3((Nc + 127) / 128, (M + 127) / 128); }

extern "C" void kernel_launch(void* const* d_in, const int* in_sizes, int n_in,
                              void* d_out, int out_size) {
    const float* x     = (const float*)d_in[0];
    const int*   ei    = (const int*)d_in[1];
    const float* ea    = (const float*)d_in[2];
    const float* W1    = (const float*)d_in[3];
    const float* a1s   = (const float*)d_in[4];
    const float* a1d   = (const float*)d_in[5];
    const float* b1    = (const float*)d_in[6];
    const float* W2    = (const float*)d_in[7];
    const float* a2s   = (const float*)d_in[8];
    const float* a2d   = (const float*)d_in[9];
    const float* b2    = (const float*)d_in[10];
    const float* W3    = (const float*)d_in[11];
    const float* a3s   = (const float*)d_in[12];
    const float* a3d   = (const float*)d_in[13];
    const float* b3    = (const float*)d_in[14];
    const float* bn1g  = (const float*)d_in[15];
    const float* bn1b  = (const float*)d_in[16];
    const float* bn2g  = (const float*)d_in[17];
    const float* bn2b  = (const float*)d_in[18];
    const float* mlpW1 = (const float*)d_in[19];
    const float* mlpb1 = (const float*)d_in[20];
    const float* mlpW2 = (const float*)d_in[21];
    const float* mlpb2 = (const float*)d_in[22];
    const float* fcW   = (const float*)d_in[23];
    const float* fcb   = (const float*)d_in[24];
    float* outp = (float*)d_out;

    const int OFF_W1 = 0, OFF_W2 = 32768, OFF_W3 = 98304;

    // weight pre-split (launch 0..2)
    k_wsplit<<<(32768 + 255) / 256, 256>>>(W1, 32768, OFF_W1);
    k_wsplit<<<(65536 + 255) / 256, 256>>>(W2, 65536, OFF_W2);
    k_wsplit<<<(16384 + 255) / 256, 256>>>(W3, 16384, OFF_W3);

    // launch 3,4: deg init + hist
    k_init_deg<<<(NN + 255) / 256, 256>>>();
    k_hist<<<(EE + 255) / 256, 256>>>(ei);

    // launch 5: layer-1 GEMM  (profiled by ncu -s 5)
    k_gemm_tf32<0><<<gemm_grid(NN, C1), 256>>>(x, OFF_W1, NN, 128, C1);

    // CSR scan + scatter
    k_scan1<<<196, 256>>>();
    k_scan2<<<1, 256>>>();
    k_scan3<<<(NN + 255) / 256, 256>>>();
    k_scatter<<<(ETOT + 255) / 256, 256>>>(ei);

    const int aggBlocks = (NN * 32 + 255) / 256;
    const int bnApplyBlocks = (int)(((size_t)NN * C1 + 255) / 256);

    // ---- layer 1 (GEMM already issued above)
    k_lsld<<<NN, C1>>>(a1s, a1d, C1);
    k_aggregate<4, 0><<<aggBlocks, 256>>>(b1);
    k_bn_zero<<<1, C1>>>();
    k_bn_stats<<<512, C1>>>();
    k_bn_finalize<<<1, C1>>>();
    k_bn_apply<<<bnApplyBlocks, 256>>>(bn1g, bn1b);

    // ---- layer 2: g_feat @ W2[256,256]
    k_gemm_tf32<1><<<gemm_grid(NN, C1), 256>>>(nullptr, OFF_W2, NN, C1, C1);
    k_lsld<<<NN, C1>>>(a2s, a2d, C1);
    k_aggregate<4, 0><<<aggBlocks, 256>>>(b2);
    k_bn_zero<<<1, C1>>>();
    k_bn_stats<<<512, C1>>>();
    k_bn_finalize<<<1, C1>>>();
    k_bn_apply<<<bnApplyBlocks, 256>>>(bn2g, bn2b);

    // ---- layer 3: g_feat @ W3[256,64], 1 head
    k_gemm_tf32<1><<<gemm_grid(NN, HIDV), 256>>>(nullptr, OFF_W3, NN, C1, HIDV);
    k_lsld<<<NN, HIDV>>>(a3s, a3d, HIDV);
    k_aggregate<1, 1><<<aggBlocks, 256>>>(b3);

    // ---- final scorer
    k_prep_final<<<1, 64>>>(mlpW2, mlpb2, fcW, fcb);
    k_node_scalars<<<(NN * 32 + 255) / 256, 256>>>(fcW);
    k_edge_out<<<(EE + 255) / 256, 256>>>(ei, ea, mlpW1, mlpb1, outp);

    (void)in_sizes; (void)n_in; (void)out_size;
}

// round 7
// speedup vs baseline: 1.2293x; 1.0248x over previous
#include <cuda_runtime.h>
#include <cuda_fp16.h>

#define NN 50000
#define EE 1600000
#define ETOT (EE + NN)
#define C1 256
#define HIDV 64
#define SLOPE 0.2f

// ------------------------- scratch (static device globals) -------------------------
__device__ __align__(16) float  g_hw[(size_t)NN * C1];     // GEMM output fp32 (for lsld)
__device__ __align__(16) __half g_hwh[(size_t)NN * C1];    // GEMM output fp16 (for gather)
__device__ __align__(16) float  g_feat[(size_t)NN * C1];   // post-BN features
__device__ __align__(16) float  g_agg[(size_t)NN * C1];    // attention aggregate
__device__ __align__(16) float  g_h3[(size_t)NN * HIDV];   // layer-3 output
__device__ __align__(16) float  g_ls[NN * 4];
__device__ __align__(16) float  g_ld[NN * 4];
__device__ int   g_deg[NN];
__device__ int   g_off[NN + 1];
__device__ int   g_cur[NN];
__device__ int   g_csr[ETOT];
__device__ int   g_bsum[256];
__device__ float g_bnsum[C1];
__device__ float g_bnsq[C1];
__device__ float g_mu[C1];
__device__ float g_rstd[C1];
__device__ float g_w2v[HIDV];
__device__ float g_cb;
__device__ float g_hs[NN];
__device__ float g_hd[NN];
// pre-split tf32 weights: W1@0(32768) W2@32768(65536) W3@98304(16384) mlpW1@114688(1024)
__device__ __align__(16) unsigned g_whi[115712];
__device__ __align__(16) unsigned g_wlo[115712];

// ------------------------- tf32 helpers -------------------------
__device__ __forceinline__ void split_tf32(float x, unsigned& hi, unsigned& lo) {
    unsigned h;
    asm("cvt.rna.tf32.f32 %0, %1;" : "=r"(h) : "f"(x));
    float l = x - __uint_as_float(h);
    unsigned lb;
    asm("cvt.rna.tf32.f32 %0, %1;" : "=r"(lb) : "f"(l));
    hi = h; lo = lb;
}

__device__ __forceinline__ void mma_tf32(float* c, const unsigned* a, const unsigned* b) {
    asm volatile("mma.sync.aligned.m16n8k8.row.col.f32.tf32.tf32.f32 "
                 "{%0,%1,%2,%3}, {%4,%5,%6,%7}, {%8,%9}, {%0,%1,%2,%3};"
                 : "+f"(c[0]), "+f"(c[1]), "+f"(c[2]), "+f"(c[3])
                 : "r"(a[0]), "r"(a[1]), "r"(a[2]), "r"(a[3]),
                   "r"(b[0]), "r"(b[1]));
}

// ------------------------- weight pre-split -------------------------
__global__ void k_wsplit(const float* __restrict__ W, int count, int offset) {
    int i = blockIdx.x * blockDim.x + threadIdx.x;
    if (i < count) {
        unsigned h, l;
        split_tf32(W[i], h, l);
        g_whi[offset + i] = h;
        g_wlo[offset + i] = l;
    }
}

// ------------------------- CSR build -------------------------
__global__ void k_init_deg() {
    int i = blockIdx.x * blockDim.x + threadIdx.x;
    if (i < NN) g_deg[i] = 1;
}

__global__ void k_hist(const int* __restrict__ ei) {
    int e = blockIdx.x * blockDim.x + threadIdx.x;
    if (e < EE) atomicAdd(&g_deg[ei[EE + e]], 1);
}

__global__ void k_scan1() {
    __shared__ int sh[256];
    int t = threadIdx.x;
    int i = blockIdx.x * 256 + t;
    int v = (i < NN) ? g_deg[i] : 0;
    sh[t] = v;
    __syncthreads();
#pragma unroll
    for (int st = 1; st < 256; st <<= 1) {
        int a = (t >= st) ? sh[t - st] : 0;
        __syncthreads();
        sh[t] += a;
        __syncthreads();
    }
    if (i < NN) g_off[i] = sh[t] - v;
    if (t == 255) g_bsum[blockIdx.x] = sh[255];
}

__global__ void k_scan2() {
    __shared__ int sh[256];
    int t = threadIdx.x;
    int v = (t < 196) ? g_bsum[t] : 0;
    sh[t] = v;
    __syncthreads();
#pragma unroll
    for (int st = 1; st < 256; st <<= 1) {
        int a = (t >= st) ? sh[t - st] : 0;
        __syncthreads();
        sh[t] += a;
        __syncthreads();
    }
    g_bsum[t] = sh[t] - v;
    if (t == 255) g_off[NN] = sh[255];
}

__global__ void k_scan3() {
    int i = blockIdx.x * blockDim.x + threadIdx.x;
    if (i < NN) {
        int o = g_off[i] + g_bsum[i >> 8];
        g_off[i] = o;
        g_cur[i] = o;
    }
}

__global__ void k_scatter(const int* __restrict__ ei) {
    int e = blockIdx.x * blockDim.x + threadIdx.x;
    if (e >= ETOT) return;
    int s, d;
    if (e < EE) { s = ei[e]; d = ei[EE + e]; }
    else        { s = e - EE; d = e - EE; }
    int pos = atomicAdd(&g_cur[d], 1);
    g_csr[pos] = s;
}

// ------------------------- TF32 split GEMM: A and B hi/lo pre-split in smem -----------
#define AS_STR 20
#define BS_STR 136

template <int A_SRC>
__global__ __launch_bounds__(256, 2) void k_gemm_tf32(const float* __restrict__ Aparam,
                                                      int boff, int M, int K, int Nc) {
    const float* A = (A_SRC == 0) ? Aparam : (const float*)g_feat;
    __shared__ unsigned Ah[128][AS_STR];
    __shared__ unsigned Al[128][AS_STR];
    __shared__ unsigned Bh[16][BS_STR];
    __shared__ unsigned Bl[16][BS_STR];

    int t = threadIdx.x;
    int lane = t & 31;
    int wid = t >> 5;
    int warpM = (wid & 3) * 32;
    int warpN = (wid >> 2) * 64;
    int rowBase = blockIdx.y * 128;
    int colBase = blockIdx.x * 128;

    float acc[2][8][4];
#pragma unroll
    for (int mt = 0; mt < 2; mt++)
#pragma unroll
        for (int nt = 0; nt < 8; nt++)
#pragma unroll
            for (int r = 0; r < 4; r++) acc[mt][nt][r] = 0.f;

    for (int k0 = 0; k0 < K; k0 += 16) {
        // A tile 128x16 load + split
#pragma unroll
        for (int q = 0; q < 2; q++) {
            int i = t + 256 * q;
            int row = i >> 2, kk = (i & 3) * 4;
            int gr = rowBase + row;
            float4 v = make_float4(0.f, 0.f, 0.f, 0.f);
            if (gr < M)
                v = *reinterpret_cast<const float4*>(A + (size_t)gr * K + k0 + kk);
            unsigned h0, l0, h1, l1, h2, l2, h3, l3;
            split_tf32(v.x, h0, l0); split_tf32(v.y, h1, l1);
            split_tf32(v.z, h2, l2); split_tf32(v.w, h3, l3);
            Ah[row][kk] = h0; Ah[row][kk + 1] = h1; Ah[row][kk + 2] = h2; Ah[row][kk + 3] = h3;
            Al[row][kk] = l0; Al[row][kk + 1] = l1; Al[row][kk + 2] = l2; Al[row][kk + 3] = l3;
        }
        // B hi/lo tiles 16x128
#pragma unroll
        for (int q = 0; q < 2; q++) {
            int i = t + 256 * q;
            int kk = i >> 5, c4 = (i & 31) * 4;
            int gc = colBase + c4;
            uint4 vh = make_uint4(0u, 0u, 0u, 0u);
            uint4 vl = make_uint4(0u, 0u, 0u, 0u);
            if (gc + 3 < Nc) {
                size_t idx = (size_t)boff + (size_t)(k0 + kk) * Nc + gc;
                vh = *reinterpret_cast<const uint4*>(g_whi + idx);
                vl = *reinterpret_cast<const uint4*>(g_wlo + idx);
            }
            *reinterpret_cast<uint4*>(&Bh[kk][c4]) = vh;
            *reinterpret_cast<uint4*>(&Bl[kk][c4]) = vl;
        }
        __syncthreads();

#pragma unroll
        for (int ks = 0; ks < 16; ks += 8) {
            unsigned ahi[2][4], alo[2][4];
            int ar = warpM + (lane >> 2);
            int ak = ks + (lane & 3);
#pragma unroll
            for (int mt = 0; mt < 2; mt++) {
                ahi[mt][0] = Ah[ar + mt * 16][ak];      alo[mt][0] = Al[ar + mt * 16][ak];
                ahi[mt][1] = Ah[ar + mt * 16 + 8][ak];  alo[mt][1] = Al[ar + mt * 16 + 8][ak];
                ahi[mt][2] = Ah[ar + mt * 16][ak + 4];  alo[mt][2] = Al[ar + mt * 16][ak + 4];
                ahi[mt][3] = Ah[ar + mt * 16 + 8][ak + 4]; alo[mt][3] = Al[ar + mt * 16 + 8][ak + 4];
            }
            int bk = ks + (lane & 3);
#pragma unroll
            for (int nt = 0; nt < 8; nt++) {
                int bn = warpN + nt * 8 + (lane >> 2);
                unsigned bhi[2], blo[2];
                bhi[0] = Bh[bk][bn];     bhi[1] = Bh[bk + 4][bn];
                blo[0] = Bl[bk][bn];     blo[1] = Bl[bk + 4][bn];
#pragma unroll
                for (int mt = 0; mt < 2; mt++) {
                    mma_tf32(acc[mt][nt], ahi[mt], bhi);
                    mma_tf32(acc[mt][nt], alo[mt], bhi);
                    mma_tf32(acc[mt][nt], ahi[mt], blo);
                }
            }
        }
        __syncthreads();
    }

#pragma unroll
    for (int mt = 0; mt < 2; mt++) {
#pragma unroll
        for (int nt = 0; nt < 8; nt++) {
            int row0 = rowBase + warpM + mt * 16 + (lane >> 2);
            int col0 = colBase + warpN + nt * 8 + (lane & 3) * 2;
            if (col0 < Nc) {
                if (row0 < M) {
                    *reinterpret_cast<float2*>(g_hw + (size_t)row0 * Nc + col0) =
                        make_float2(acc[mt][nt][0], acc[mt][nt][1]);
                    *reinterpret_cast<__half2*>(g_hwh + (size_t)row0 * Nc + col0) =
                        __floats2half2_rn(acc[mt][nt][0], acc[mt][nt][1]);
                }
                if (row0 + 8 < M) {
                    *reinterpret_cast<float2*>(g_hw + (size_t)(row0 + 8) * Nc + col0) =
                        make_float2(acc[mt][nt][2], acc[mt][nt][3]);
                    *reinterpret_cast<__half2*>(g_hwh + (size_t)(row0 + 8) * Nc + col0) =
                        __floats2half2_rn(acc[mt][nt][2], acc[mt][nt][3]);
                }
            }
        }
    }
}

// ------------------------- ls/ld; reads g_hw --------------
__global__ void k_lsld(const float* __restrict__ as, const float* __restrict__ ad, int C) {
    __shared__ float s1[256], s2[256];
    int n = blockIdx.x;
    int t = threadIdx.x;
    float v = g_hw[(size_t)n * C + t];
    s1[t] = v * as[t];
    s2[t] = v * ad[t];
    __syncthreads();
    for (int st = 32; st >= 1; st >>= 1) {
        if ((t & 63) < st) { s1[t] += s1[t + st]; s2[t] += s2[t + st]; }
        __syncthreads();
    }
    if ((t & 63) == 0) {
        int h = t >> 6;
        int H = C >> 6;
        g_ls[n * H + h] = s1[t];
        g_ld[n * H + h] = s2[t];
    }
}

// ------------------------- GAT aggregate: warp/dst, fp16 feature gather ---------------
template <int H, int DSTSEL>
__global__ void k_aggregate(const float* __restrict__ bias) {
    float* out = (DSTSEL == 0) ? (float*)g_agg : (float*)g_h3;
    int w = (blockIdx.x * blockDim.x + threadIdx.x) >> 5;
    int lane = threadIdx.x & 31;
    if (w >= NN) return;
    int beg = g_off[w], end = g_off[w + 1];

    if (H == 4) {
        float4 ldv = *reinterpret_cast<const float4*>(g_ld + w * 4);
        float s0 = 0.f, s1 = 0.f, s2 = 0.f, s3 = 0.f;
        float a0 = 0.f, a1 = 0.f, a2 = 0.f, a3 = 0.f;
        float a4 = 0.f, a5 = 0.f, a6 = 0.f, a7 = 0.f;
        int hd = lane >> 3;  // 8 consecutive channels per lane -> one head
        for (int i = beg; i < end; i++) {
            int s = g_csr[i];
            float4 lsv = *reinterpret_cast<const float4*>(g_ls + s * 4);
            float l0 = lsv.x + ldv.x; l0 = l0 > 0.f ? l0 : SLOPE * l0;
            float l1 = lsv.y + ldv.y; l1 = l1 > 0.f ? l1 : SLOPE * l1;
            float l2 = lsv.z + ldv.z; l2 = l2 > 0.f ? l2 : SLOPE * l2;
            float l3 = lsv.w + ldv.w; l3 = l3 > 0.f ? l3 : SLOPE * l3;
            float p0 = __expf(l0), p1 = __expf(l1), p2 = __expf(l2), p3 = __expf(l3);
            s0 += p0; s1 += p1; s2 += p2; s3 += p3;
            float p = (hd == 0) ? p0 : (hd == 1) ? p1 : (hd == 2) ? p2 : p3;
            uint4 v = reinterpret_cast<const uint4*>(g_hwh + (size_t)s * 256)[lane];
            float2 f0 = __half22float2(*reinterpret_cast<__half2*>(&v.x));
            float2 f1 = __half22float2(*reinterpret_cast<__half2*>(&v.y));
            float2 f2 = __half22float2(*reinterpret_cast<__half2*>(&v.z));
            float2 f3 = __half22float2(*reinterpret_cast<__half2*>(&v.w));
            a0 += p * f0.x; a1 += p * f0.y; a2 += p * f1.x; a3 += p * f1.y;
            a4 += p * f2.x; a5 += p * f2.y; a6 += p * f3.x; a7 += p * f3.y;
        }
        float ss = (hd == 0) ? s0 : (hd == 1) ? s1 : (hd == 2) ? s2 : s3;
        float inv = 1.f / (ss + 1e-16f);
        const float* bp = bias + lane * 8;
        float4 bv0 = *reinterpret_cast<const float4*>(bp);
        float4 bv1 = *reinterpret_cast<const float4*>(bp + 4);
        float* op = out + (size_t)w * 256 + lane * 8;
        *reinterpret_cast<float4*>(op) =
            make_float4(a0 * inv + bv0.x, a1 * inv + bv0.y, a2 * inv + bv0.z, a3 * inv + bv0.w);
        *reinterpret_cast<float4*>(op + 4) =
            make_float4(a4 * inv + bv1.x, a5 * inv + bv1.y, a6 * inv + bv1.z, a7 * inv + bv1.w);
    } else {
        float ldh = g_ld[w];
        float ssum = 0.f;
        float ax = 0.f, ay = 0.f;
        for (int i = beg; i < end; i++) {
            int s = g_csr[i];
            float lg = g_ls[s] + ldh;
            lg = lg > 0.f ? lg : SLOPE * lg;
            float p = __expf(lg);
            ssum += p;
            __half2 hv = reinterpret_cast<const __half2*>(g_hwh + (size_t)s * 64)[lane];
            float2 v = __half22float2(hv);
            ax += p * v.x; ay += p * v.y;
        }
        float inv = 1.f / (ssum + 1e-16f);
        float2 b = reinterpret_cast<const float2*>(bias)[lane];
        reinterpret_cast<float2*>(out + (size_t)w * 64)[lane] =
            make_float2(ax * inv + b.x, ay * inv + b.y);
    }
}

// ------------------------- ELU + BatchNorm -------------------------
__device__ __forceinline__ float eluf(float x) { return x > 0.f ? x : expm1f(x); }

__global__ void k_bn_zero() {
    int t = threadIdx.x;
    g_bnsum[t] = 0.f;
    g_bnsq[t] = 0.f;
}

__global__ void k_bn_stats() {
    int t = threadIdx.x;
    float s = 0.f, s2 = 0.f;
    for (int r = blockIdx.x; r < NN; r += gridDim.x) {
        float v = eluf(g_agg[(size_t)r * C1 + t]);
        s += v;
        s2 += v * v;
    }
    atomicAdd(&g_bnsum[t], s);
    atomicAdd(&g_bnsq[t], s2);
}

__global__ void k_bn_finalize() {
    int t = threadIdx.x;
    float mu = g_bnsum[t] / (float)NN;
    float var = g_bnsq[t] / (float)NN - mu * mu;
    g_mu[t] = mu;
    g_rstd[t] = rsqrtf(var + 1e-5f);
}

__global__ void k_bn_apply(const float* __restrict__ gam, const float* __restrict__ bet) {
    size_t i = (size_t)blockIdx.x * blockDim.x + threadIdx.x;
    if (i >= (size_t)NN * C1) return;
    int c = (int)(i & (C1 - 1));
    float v = eluf(g_agg[i]);
    g_feat[i] = (v - g_mu[c]) * g_rstd[c] * gam[c] + bet[c];
}

// ------------------------- final scorer -------------------------
__global__ void k_prep_final(const float* __restrict__ mlpW2, const float* __restrict__ mlpb2,
                             const float* __restrict__ fcW, const float* __restrict__ fcb) {
    int j = threadIdx.x;
    float s = 0.f;
    for (int k = 0; k < 64; k++) s += mlpW2[j * 64 + k] * fcW[128 + k];
    g_w2v[j] = s;
    if (j == 0) {
        float c = fcb[0];
        for (int k = 0; k < 64; k++) c += mlpb2[k] * fcW[128 + k];
        g_cb = c;
    }
}

__global__ void k_node_scalars(const float* __restrict__ fcW) {
    int w = (blockIdx.x * blockDim.x + threadIdx.x) >> 5;
    int lane = threadIdx.x & 31;
    if (w >= NN) return;
    const float* h = g_h3 + (size_t)w * 64;
    float v0 = h[lane], v1 = h[lane + 32];
    float a = v0 * fcW[lane] + v1 * fcW[lane + 32];
    float b = v0 * fcW[64 + lane] + v1 * fcW[96 + lane];
    for (int off = 16; off; off >>= 1) {
        a += __shfl_xor_sync(0xffffffffu, a, off);
        b += __shfl_xor_sync(0xffffffffu, b, off);
    }
    if (lane == 0) { g_hs[w] = a; g_hd[w] = b; }
}

// ------------------------- edge scorer: tf32 MMA edge-MLP, folded -------------------
// 256 thr = 8 warps x 16 edges = 128 edges/block. Grid = EE/128 = 12500 exactly.
#define OFF_MW 114688
__global__ __launch_bounds__(256) void k_edge_out(const int* __restrict__ ei,
                                                  const float* __restrict__ ea,
                                                  const float* __restrict__ mlpb1,
                                                  float* __restrict__ outp) {
    __shared__ float eas[128][17];
    __shared__ unsigned w1h[16][68];
    __shared__ unsigned w1l[16][68];
    __shared__ float b1s[64];
    __shared__ float w2vs[64];
    int t = threadIdx.x;
    int lane = t & 31;
    int wrp = t >> 5;
    int eBase = blockIdx.x * 128;

    // stage mlp weights (hi/lo) + bias + w2v
#pragma unroll
    for (int q = 0; q < 4; q++) {
        int idx = t + 256 * q;   // 1024 entries
        int k = idx >> 6, n = idx & 63;
        w1h[k][n] = g_whi[OFF_MW + idx];
        w1l[k][n] = g_wlo[OFF_MW + idx];
    }
    if (t < 64) { b1s[t] = mlpb1[t]; w2vs[t] = g_w2v[t]; }
    // stage edge attrs 128x16
#pragma unroll
    for (int q = 0; q < 2; q++) {
        int j = t + 256 * q;     // float4 index, 512 total
        int row = j >> 2, kk = (j & 3) * 4;
        float4 v = *reinterpret_cast<const float4*>(ea + (size_t)(eBase + row) * 16 + kk);
        eas[row][kk] = v.x; eas[row][kk + 1] = v.y;
        eas[row][kk + 2] = v.z; eas[row][kk + 3] = v.w;
    }
    __syncthreads();

    int wr = wrp * 16;
    int ar = lane >> 2, ak = lane & 3;
    // A fragments for kf=0,1 with tf32 split
    unsigned ahi[2][4], alo[2][4];
#pragma unroll
    for (int kf = 0; kf < 2; kf++) {
        split_tf32(eas[wr + ar][kf * 8 + ak],          ahi[kf][0], alo[kf][0]);
        split_tf32(eas[wr + ar + 8][kf * 8 + ak],      ahi[kf][1], alo[kf][1]);
        split_tf32(eas[wr + ar][kf * 8 + ak + 4],      ahi[kf][2], alo[kf][2]);
        split_tf32(eas[wr + ar + 8][kf * 8 + ak + 4],  ahi[kf][3], alo[kf][3]);
    }

    float dr0 = 0.f, dr1 = 0.f;
    int col0 = (lane & 3) * 2;
#pragma unroll
    for (int nt = 0; nt < 8; nt++) {
        float acc[4] = {0.f, 0.f, 0.f, 0.f};
        int bn = nt * 8 + (lane >> 2);
#pragma unroll
        for (int kf = 0; kf < 2; kf++) {
            int bk = kf * 8 + (lane & 3);
            unsigned bhi[2], blo[2];
            bhi[0] = w1h[bk][bn];     bhi[1] = w1h[bk + 4][bn];
            blo[0] = w1l[bk][bn];     blo[1] = w1l[bk + 4][bn];
            mma_tf32(acc, ahi[kf], bhi);
            mma_tf32(acc, alo[kf], bhi);
            mma_tf32(acc, ahi[kf], blo);
        }
        int c = nt * 8 + col0;
        float b0 = b1s[c], b1 = b1s[c + 1];
        float wv0 = w2vs[c], wv1 = w2vs[c + 1];
        dr0 += fmaxf(acc[0] + b0, 0.f) * wv0 + fmaxf(acc[1] + b1, 0.f) * wv1;
        dr1 += fmaxf(acc[2] + b0, 0.f) * wv0 + fmaxf(acc[3] + b1, 0.f) * wv1;
    }
    // reduce over the 4 lanes sharing a row (lane&3)
    dr0 += __shfl_xor_sync(0xffffffffu, dr0, 1);
    dr0 += __shfl_xor_sync(0xffffffffu, dr0, 2);
    dr1 += __shfl_xor_sync(0xffffffffu, dr1, 1);
    dr1 += __shfl_xor_sync(0xffffffffu, dr1, 2);

    if ((lane & 3) == 0) {
        int r = lane >> 2;
        int e0 = eBase + wr + r;
        int e1 = e0 + 8;
        int s0 = ei[e0], d0 = ei[EE + e0];
        int s1 = ei[e1], d1 = ei[EE + e1];
        outp[e0] = g_hs[s0] + g_hd[d0] + dr0 + g_cb;
        outp[e1] = g_hs[s1] + g_hd[d1] + dr1 + g_cb;
    }
}

// ------------------------- launch -------------------------
static inline dim3 gemm_grid(int M, int Nc) { return dim3((Nc + 127) / 128, (M + 127) / 128); }

extern "C" void kernel_launch(void* const* d_in, const int* in_sizes, int n_in,
                              void* d_out, int out_size) {
    const float* x     = (const float*)d_in[0];
    const int*   ei    = (const int*)d_in[1];
    const float* ea    = (const float*)d_in[2];
    const float* W1    = (const float*)d_in[3];
    const float* a1s   = (const float*)d_in[4];
    const float* a1d   = (const float*)d_in[5];
    const float* b1    = (const float*)d_in[6];
    const float* W2    = (const float*)d_in[7];
    const float* a2s   = (const float*)d_in[8];
    const float* a2d   = (const float*)d_in[9];
    const float* b2    = (const float*)d_in[10];
    const float* W3    = (const float*)d_in[11];
    const float* a3s   = (const float*)d_in[12];
    const float* a3d   = (const float*)d_in[13];
    const float* b3    = (const float*)d_in[14];
    const float* bn1g  = (const float*)d_in[15];
    const float* bn1b  = (const float*)d_in[16];
    const float* bn2g  = (const float*)d_in[17];
    const float* bn2b  = (const float*)d_in[18];
    const float* mlpW1 = (const float*)d_in[19];
    const float* mlpb1 = (const float*)d_in[20];
    const float* mlpW2 = (const float*)d_in[21];
    const float* mlpb2 = (const float*)d_in[22];
    const float* fcW   = (const float*)d_in[23];
    const float* fcb   = (const float*)d_in[24];
    float* outp = (float*)d_out;

    const int OFF_W1 = 0, OFF_W2 = 32768, OFF_W3 = 98304;

    // launches 0..2
    k_init_deg<<<(NN + 255) / 256, 256>>>();
    k_hist<<<(EE + 255) / 256, 256>>>(ei);
    k_wsplit<<<(32768 + 255) / 256, 256>>>(W1, 32768, OFF_W1);
    // launch #3 (profiled by ncu): layer-1 GEMM
    k_gemm_tf32<0><<<gemm_grid(NN, C1), 256>>>(x, OFF_W1, NN, 128, C1);

    k_wsplit<<<(65536 + 255) / 256, 256>>>(W2, 65536, OFF_W2);
    k_wsplit<<<(16384 + 255) / 256, 256>>>(W3, 16384, OFF_W3);
    k_wsplit<<<4, 256>>>(mlpW1, 1024, OFF_MW);

    k_scan1<<<196, 256>>>();
    k_scan2<<<1, 256>>>();
    k_scan3<<<(NN + 255) / 256, 256>>>();
    k_scatter<<<(ETOT + 255) / 256, 256>>>(ei);

    const int aggBlocks = (NN * 32 + 255) / 256;
    const int bnApplyBlocks = (int)(((size_t)NN * C1 + 255) / 256);

    // ---- layer 1 (GEMM already issued)
    k_lsld<<<NN, C1>>>(a1s, a1d, C1);
    k_aggregate<4, 0><<<aggBlocks, 256>>>(b1);
    k_bn_zero<<<1, C1>>>();
    k_bn_stats<<<512, C1>>>();
    k_bn_finalize<<<1, C1>>>();
    k_bn_apply<<<bnApplyBlocks, 256>>>(bn1g, bn1b);

    // ---- layer 2
    k_gemm_tf32<1><<<gemm_grid(NN, C1), 256>>>(nullptr, OFF_W2, NN, C1, C1);
    k_lsld<<<NN, C1>>>(a2s, a2d, C1);
    k_aggregate<4, 0><<<aggBlocks, 256>>>(b2);
    k_bn_zero<<<1, C1>>>();
    k_bn_stats<<<512, C1>>>();
    k_bn_finalize<<<1, C1>>>();
    k_bn_apply<<<bnApplyBlocks, 256>>>(bn2g, bn2b);

    // ---- layer 3
    k_gemm_tf32<1><<<gemm_grid(NN, HIDV), 256>>>(nullptr, OFF_W3, NN, C1, HIDV);
    k_lsld<<<NN, HIDV>>>(a3s, a3d, HIDV);
    k_aggregate<1, 1><<<aggBlocks, 256>>>(b3);

    // ---- final scorer
    k_prep_final<<<1, 64>>>(mlpW2, mlpb2, fcW, fcb);
    k_node_scalars<<<(NN * 32 + 255) / 256, 256>>>(fcW);
    k_edge_out<<<12500, 256>>>(ei, ea, mlpb1, outp);

    (void)in_sizes; (void)n_in; (void)out_size;
}

// round 8
// speedup vs baseline: 1.5019x; 1.2217x over previous
#include <cuda_runtime.h>
#include <cuda_fp16.h>

#define NN 50000
#define EE 1600000
#define ETOT (EE + NN)
#define C1 256
#define HIDV 64
#define SLOPE 0.2f

// ------------------------- scratch (static device globals) -------------------------
__device__ __align__(16) __half g_hwh[(size_t)NN * C1];    // GEMM output fp16 (gather)
__device__ __align__(16) float  g_feat[(size_t)NN * C1];   // post-BN features
__device__ __align__(16) float  g_agg[(size_t)NN * C1];    // attention aggregate
__device__ __align__(16) float  g_h3[(size_t)NN * HIDV];   // layer-3 output
__device__ __align__(16) float  g_ls[NN * 4];
__device__ __align__(16) float  g_ld[NN * 4];
__device__ int   g_deg[NN];
__device__ int   g_off[NN + 1];
__device__ int   g_cur[NN];
__device__ int   g_csr[ETOT];
__device__ int   g_bsum[256];
__device__ float g_bnsum[C1];
__device__ float g_bnsq[C1];
__device__ float g_mu[C1];
__device__ float g_rstd[C1];
__device__ float g_w2v[HIDV];
__device__ float g_cb;
__device__ float g_hs[NN];
__device__ float g_hd[NN];
// pre-split tf32 weights: W1@0(32768) W2@32768(65536) W3@98304(16384) mlpW1@114688(1024)
__device__ __align__(16) unsigned g_whi[115712];
__device__ __align__(16) unsigned g_wlo[115712];

// ------------------------- tf32 helpers -------------------------
__device__ __forceinline__ void split_tf32(float x, unsigned& hi, unsigned& lo) {
    unsigned h;
    asm("cvt.rna.tf32.f32 %0, %1;" : "=r"(h) : "f"(x));
    float l = x - __uint_as_float(h);
    unsigned lb;
    asm("cvt.rna.tf32.f32 %0, %1;" : "=r"(lb) : "f"(l));
    hi = h; lo = lb;
}

__device__ __forceinline__ void mma_tf32(float* c, const unsigned* a, const unsigned* b) {
    asm volatile("mma.sync.aligned.m16n8k8.row.col.f32.tf32.tf32.f32 "
                 "{%0,%1,%2,%3}, {%4,%5,%6,%7}, {%8,%9}, {%0,%1,%2,%3};"
                 : "+f"(c[0]), "+f"(c[1]), "+f"(c[2]), "+f"(c[3])
                 : "r"(a[0]), "r"(a[1]), "r"(a[2]), "r"(a[3]),
                   "r"(b[0]), "r"(b[1]));
}

// ------------------------- weight pre-split -------------------------
__global__ void k_wsplit(const float* __restrict__ W, int count, int offset) {
    int i = blockIdx.x * blockDim.x + threadIdx.x;
    if (i < count) {
        unsigned h, l;
        split_tf32(W[i], h, l);
        g_whi[offset + i] = h;
        g_wlo[offset + i] = l;
    }
}

// ------------------------- init / zero kernels -------------------------
__global__ void k_init() {   // grid 196 x 256
    int i = blockIdx.x * blockDim.x + threadIdx.x;
    if (i < NN) g_deg[i] = 1;
    for (int j = i; j < NN * 4; j += 50176) { g_ls[j] = 0.f; g_ld[j] = 0.f; }
    if (i < C1) { g_bnsum[i] = 0.f; g_bnsq[i] = 0.f; }
}

__global__ void k_zero2() {  // grid 196 x 256; zero ls/ld + bn accumulators
    int i = blockIdx.x * blockDim.x + threadIdx.x;
    for (int j = i; j < NN * 4; j += 50176) { g_ls[j] = 0.f; g_ld[j] = 0.f; }
    if (i < C1) { g_bnsum[i] = 0.f; g_bnsq[i] = 0.f; }
}

// ------------------------- CSR build -------------------------
__global__ void k_hist(const int* __restrict__ ei) {
    int e = blockIdx.x * blockDim.x + threadIdx.x;
    if (e < EE) atomicAdd(&g_deg[ei[EE + e]], 1);
}

__global__ void k_scan1() {
    __shared__ int sh[256];
    int t = threadIdx.x;
    int i = blockIdx.x * 256 + t;
    int v = (i < NN) ? g_deg[i] : 0;
    sh[t] = v;
    __syncthreads();
#pragma unroll
    for (int st = 1; st < 256; st <<= 1) {
        int a = (t >= st) ? sh[t - st] : 0;
        __syncthreads();
        sh[t] += a;
        __syncthreads();
    }
    if (i < NN) g_off[i] = sh[t] - v;
    if (t == 255) g_bsum[blockIdx.x] = sh[255];
}

__global__ void k_scan2() {
    __shared__ int sh[256];
    int t = threadIdx.x;
    int v = (t < 196) ? g_bsum[t] : 0;
    sh[t] = v;
    __syncthreads();
#pragma unroll
    for (int st = 1; st < 256; st <<= 1) {
        int a = (t >= st) ? sh[t - st] : 0;
        __syncthreads();
        sh[t] += a;
        __syncthreads();
    }
    g_bsum[t] = sh[t] - v;
    if (t == 255) g_off[NN] = sh[255];
}

__global__ void k_scan3() {
    int i = blockIdx.x * blockDim.x + threadIdx.x;
    if (i < NN) {
        int o = g_off[i] + g_bsum[i >> 8];
        g_off[i] = o;
        g_cur[i] = o;
    }
}

__global__ void k_scatter(const int* __restrict__ ei) {
    int e = blockIdx.x * blockDim.x + threadIdx.x;
    if (e >= ETOT) return;
    int s, d;
    if (e < EE) { s = ei[e]; d = ei[EE + e]; }
    else        { s = e - EE; d = e - EE; }
    int pos = atomicAdd(&g_cur[d], 1);
    g_csr[pos] = s;
}

// ------------------------- TF32 GEMM: 2-stage cp.async pipeline + fused ls/ld ---------
// dyn smem per stage: Ah 128x20 u32 (10240B) | Al (10240B) | Bh 16x136 (8704B) | Bl (8704B)
#define ST_SZ   37888
#define O_AL    10240
#define O_BH    20480
#define O_BL    29184
#define GEMM_SMEM (2 * ST_SZ)

template <int A_SRC>
__global__ __launch_bounds__(256, 2) void k_gemm_tf32(const float* __restrict__ Aparam,
                                                      const float* __restrict__ asv,
                                                      const float* __restrict__ adv,
                                                      int boff, int M, int K, int Nc, int H) {
    const float* A = (A_SRC == 0) ? Aparam : (const float*)g_feat;
    extern __shared__ char smx[];
    unsigned smBase = (unsigned)__cvta_generic_to_shared(smx);

    int t = threadIdx.x;
    int lane = t & 31;
    int wid = t >> 5;
    int warpM = (wid & 3) * 32;
    int warpN = (wid >> 2) * 64;
    int rowBase = blockIdx.y * 128;
    int colBase = blockIdx.x * 128;

    // per-thread staging indices
    int aRow = t >> 2, aK = (t & 3) * 4;          // A: +256 -> row+64
    int bK = t >> 5, bC = (t & 31) * 4;           // B: +256 -> kk+8

    float acc[2][8][4];
#pragma unroll
    for (int mt = 0; mt < 2; mt++)
#pragma unroll
        for (int nt = 0; nt < 8; nt++)
#pragma unroll
            for (int r = 0; r < 4; r++) acc[mt][nt][r] = 0.f;

    int nCh = K >> 4;
    float4 va[2];

    // ---- helpers as lambdas
    auto loadA = [&](int k0) {
#pragma unroll
        for (int q = 0; q < 2; q++) {
            int gr = rowBase + aRow + 64 * q;
            va[q] = make_float4(0.f, 0.f, 0.f, 0.f);
            if (gr < M)
                va[q] = *reinterpret_cast<const float4*>(A + (size_t)gr * K + k0 + aK);
        }
    };
    auto stsA = [&](int stg) {
        unsigned* Ah = reinterpret_cast<unsigned*>(smx + stg * ST_SZ);
        unsigned* Al = reinterpret_cast<unsigned*>(smx + stg * ST_SZ + O_AL);
#pragma unroll
        for (int q = 0; q < 2; q++) {
            int row = aRow + 64 * q;
            unsigned h0, l0, h1, l1, h2, l2, h3, l3;
            split_tf32(va[q].x, h0, l0); split_tf32(va[q].y, h1, l1);
            split_tf32(va[q].z, h2, l2); split_tf32(va[q].w, h3, l3);
            Ah[row * 20 + aK] = h0; Ah[row * 20 + aK + 1] = h1;
            Ah[row * 20 + aK + 2] = h2; Ah[row * 20 + aK + 3] = h3;
            Al[row * 20 + aK] = l0; Al[row * 20 + aK + 1] = l1;
            Al[row * 20 + aK + 2] = l2; Al[row * 20 + aK + 3] = l3;
        }
    };
    auto cpB = [&](int k0, int stg) {
#pragma unroll
        for (int q = 0; q < 2; q++) {
            int kk = bK + 8 * q;
            int gc = colBase + bC;
            int vbytes = (gc + 3 < Nc) ? 16 : 0;
            size_t idx = (size_t)boff + (size_t)(k0 + kk) * Nc + (vbytes ? gc : 0);
            unsigned dH = smBase + stg * ST_SZ + O_BH + (kk * 136 + bC) * 4;
            unsigned dL = smBase + stg * ST_SZ + O_BL + (kk * 136 + bC) * 4;
            asm volatile("cp.async.cg.shared.global [%0], [%1], 16, %2;"
                         :: "r"(dH), "l"(g_whi + idx), "r"(vbytes));
            asm volatile("cp.async.cg.shared.global [%0], [%1], 16, %2;"
                         :: "r"(dL), "l"(g_wlo + idx), "r"(vbytes));
        }
    };

    // ---- prologue: stage 0
    loadA(0);
    cpB(0, 0);
    asm volatile("cp.async.commit_group;" ::: "memory");
    stsA(0);

    int buf = 0;
    for (int c = 0; c < nCh; c++) {
        asm volatile("cp.async.wait_group 0;" ::: "memory");
        __syncthreads();
        if (c + 1 < nCh) {
            loadA((c + 1) * 16);
            cpB((c + 1) * 16, buf ^ 1);
            asm volatile("cp.async.commit_group;" ::: "memory");
        }
        // ---- MMAs on buf
        {
            unsigned* Ah = reinterpret_cast<unsigned*>(smx + buf * ST_SZ);
            unsigned* Al = reinterpret_cast<unsigned*>(smx + buf * ST_SZ + O_AL);
            unsigned* Bh = reinterpret_cast<unsigned*>(smx + buf * ST_SZ + O_BH);
            unsigned* Bl = reinterpret_cast<unsigned*>(smx + buf * ST_SZ + O_BL);
#pragma unroll
            for (int ks = 0; ks < 16; ks += 8) {
                unsigned ahi[2][4], alo[2][4];
                int ar = warpM + (lane >> 2);
                int ak = ks + (lane & 3);
#pragma unroll
                for (int mt = 0; mt < 2; mt++) {
                    int r0 = (ar + mt * 16) * 20;
                    int r1 = (ar + mt * 16 + 8) * 20;
                    ahi[mt][0] = Ah[r0 + ak];     alo[mt][0] = Al[r0 + ak];
                    ahi[mt][1] = Ah[r1 + ak];     alo[mt][1] = Al[r1 + ak];
                    ahi[mt][2] = Ah[r0 + ak + 4]; alo[mt][2] = Al[r0 + ak + 4];
                    ahi[mt][3] = Ah[r1 + ak + 4]; alo[mt][3] = Al[r1 + ak + 4];
                }
                int bk = ks + (lane & 3);
#pragma unroll
                for (int nt = 0; nt < 8; nt++) {
                    int bn = warpN + nt * 8 + (lane >> 2);
                    unsigned bhi[2], blo[2];
                    bhi[0] = Bh[bk * 136 + bn];       bhi[1] = Bh[(bk + 4) * 136 + bn];
                    blo[0] = Bl[bk * 136 + bn];       blo[1] = Bl[(bk + 4) * 136 + bn];
#pragma unroll
                    for (int mt = 0; mt < 2; mt++) {
                        mma_tf32(acc[mt][nt], ahi[mt], bhi);
                        mma_tf32(acc[mt][nt], alo[mt], bhi);
                        mma_tf32(acc[mt][nt], ahi[mt], blo);
                    }
                }
            }
        }
        if (c + 1 < nCh) stsA(buf ^ 1);
        buf ^= 1;
    }

    // ---- epilogue: fp16 store + fused ls/ld
#pragma unroll
    for (int mt = 0; mt < 2; mt++) {
#pragma unroll
        for (int nt = 0; nt < 8; nt++) {
            int row0 = rowBase + warpM + mt * 16 + (lane >> 2);
            int col0 = colBase + warpN + nt * 8 + (lane & 3) * 2;
            if (col0 < Nc) {
                if (row0 < M)
                    *reinterpret_cast<__half2*>(g_hwh + (size_t)row0 * Nc + col0) =
                        __floats2half2_rn(acc[mt][nt][0], acc[mt][nt][1]);
                if (row0 + 8 < M)
                    *reinterpret_cast<__half2*>(g_hwh + (size_t)(row0 + 8) * Nc + col0) =
                        __floats2half2_rn(acc[mt][nt][2], acc[mt][nt][3]);
            }
        }
    }

    if (warpN < Nc) {
        int head = (colBase + warpN) >> 6;
        float pls[2][2] = {{0.f, 0.f}, {0.f, 0.f}};
        float pld[2][2] = {{0.f, 0.f}, {0.f, 0.f}};
#pragma unroll
        for (int nt = 0; nt < 8; nt++) {
            int c0 = colBase + warpN + nt * 8 + (lane & 3) * 2;
            float2 ws = *reinterpret_cast<const float2*>(asv + c0);
            float2 wd = *reinterpret_cast<const float2*>(adv + c0);
#pragma unroll
            for (int mt = 0; mt < 2; mt++) {
                pls[mt][0] += acc[mt][nt][0] * ws.x + acc[mt][nt][1] * ws.y;
                pls[mt][1] += acc[mt][nt][2] * ws.x + acc[mt][nt][3] * ws.y;
                pld[mt][0] += acc[mt][nt][0] * wd.x + acc[mt][nt][1] * wd.y;
                pld[mt][1] += acc[mt][nt][2] * wd.x + acc[mt][nt][3] * wd.y;
            }
        }
#pragma unroll
        for (int mt = 0; mt < 2; mt++)
#pragma unroll
            for (int rr = 0; rr < 2; rr++) {
                pls[mt][rr] += __shfl_xor_sync(0xffffffffu, pls[mt][rr], 1);
                pls[mt][rr] += __shfl_xor_sync(0xffffffffu, pls[mt][rr], 2);
                pld[mt][rr] += __shfl_xor_sync(0xffffffffu, pld[mt][rr], 1);
                pld[mt][rr] += __shfl_xor_sync(0xffffffffu, pld[mt][rr], 2);
            }
        if ((lane & 3) == 0) {
#pragma unroll
            for (int mt = 0; mt < 2; mt++)
#pragma unroll
                for (int rr = 0; rr < 2; rr++) {
                    int row = rowBase + warpM + mt * 16 + (lane >> 2) + rr * 8;
                    if (row < M) {
                        atomicAdd(&g_ls[row * H + head], pls[mt][rr]);
                        atomicAdd(&g_ld[row * H + head], pld[mt][rr]);
                    }
                }
        }
    }
}

// ------------------------- GAT aggregate: warp/dst, fp16 feature gather ---------------
template <int H, int DSTSEL>
__global__ void k_aggregate(const float* __restrict__ bias) {
    float* out = (DSTSEL == 0) ? (float*)g_agg : (float*)g_h3;
    int w = (blockIdx.x * blockDim.x + threadIdx.x) >> 5;
    int lane = threadIdx.x & 31;
    if (w >= NN) return;
    int beg = g_off[w], end = g_off[w + 1];

    if (H == 4) {
        float4 ldv = *reinterpret_cast<const float4*>(g_ld + w * 4);
        float s0 = 0.f, s1 = 0.f, s2 = 0.f, s3 = 0.f;
        float a0 = 0.f, a1 = 0.f, a2 = 0.f, a3 = 0.f;
        float a4 = 0.f, a5 = 0.f, a6 = 0.f, a7 = 0.f;
        int hd = lane >> 3;
        for (int i = beg; i < end; i++) {
            int s = g_csr[i];
            float4 lsv = *reinterpret_cast<const float4*>(g_ls + s * 4);
            float l0 = lsv.x + ldv.x; l0 = l0 > 0.f ? l0 : SLOPE * l0;
            float l1 = lsv.y + ldv.y; l1 = l1 > 0.f ? l1 : SLOPE * l1;
            float l2 = lsv.z + ldv.z; l2 = l2 > 0.f ? l2 : SLOPE * l2;
            float l3 = lsv.w + ldv.w; l3 = l3 > 0.f ? l3 : SLOPE * l3;
            float p0 = __expf(l0), p1 = __expf(l1), p2 = __expf(l2), p3 = __expf(l3);
            s0 += p0; s1 += p1; s2 += p2; s3 += p3;
            float p = (hd == 0) ? p0 : (hd == 1) ? p1 : (hd == 2) ? p2 : p3;
            uint4 v = reinterpret_cast<const uint4*>(g_hwh + (size_t)s * 256)[lane];
            float2 f0 = __half22float2(*reinterpret_cast<__half2*>(&v.x));
            float2 f1 = __half22float2(*reinterpret_cast<__half2*>(&v.y));
            float2 f2 = __half22float2(*reinterpret_cast<__half2*>(&v.z));
            float2 f3 = __half22float2(*reinterpret_cast<__half2*>(&v.w));
            a0 += p * f0.x; a1 += p * f0.y; a2 += p * f1.x; a3 += p * f1.y;
            a4 += p * f2.x; a5 += p * f2.y; a6 += p * f3.x; a7 += p * f3.y;
        }
        float ss = (hd == 0) ? s0 : (hd == 1) ? s1 : (hd == 2) ? s2 : s3;
        float inv = 1.f / (ss + 1e-16f);
        const float* bp = bias + lane * 8;
        float4 bv0 = *reinterpret_cast<const float4*>(bp);
        float4 bv1 = *reinterpret_cast<const float4*>(bp + 4);
        float* op = out + (size_t)w * 256 + lane * 8;
        *reinterpret_cast<float4*>(op) =
            make_float4(a0 * inv + bv0.x, a1 * inv + bv0.y, a2 * inv + bv0.z, a3 * inv + bv0.w);
        *reinterpret_cast<float4*>(op + 4) =
            make_float4(a4 * inv + bv1.x, a5 * inv + bv1.y, a6 * inv + bv1.z, a7 * inv + bv1.w);
    } else {
        float ldh = g_ld[w];
        float ssum = 0.f;
        float ax = 0.f, ay = 0.f;
        for (int i = beg; i < end; i++) {
            int s = g_csr[i];
            float lg = g_ls[s] + ldh;
            lg = lg > 0.f ? lg : SLOPE * lg;
            float p = __expf(lg);
            ssum += p;
            __half2 hv = reinterpret_cast<const __half2*>(g_hwh + (size_t)s * 64)[lane];
            float2 v = __half22float2(hv);
            ax += p * v.x; ay += p * v.y;
        }
        float inv = 1.f / (ssum + 1e-16f);
        float2 b = reinterpret_cast<const float2*>(bias)[lane];
        reinterpret_cast<float2*>(out + (size_t)w * 64)[lane] =
            make_float2(ax * inv + b.x, ay * inv + b.y);
    }
}

// ------------------------- ELU + BatchNorm -------------------------
__device__ __forceinline__ float eluf(float x) { return x > 0.f ? x : expm1f(x); }

__global__ void k_bn_stats() {
    int t = threadIdx.x;
    float s = 0.f, s2 = 0.f;
    for (int r = blockIdx.x; r < NN; r += gridDim.x) {
        float v = eluf(g_agg[(size_t)r * C1 + t]);
        s += v;
        s2 += v * v;
    }
    atomicAdd(&g_bnsum[t], s);
    atomicAdd(&g_bnsq[t], s2);
}

__global__ void k_bn_finalize() {
    int t = threadIdx.x;
    float mu = g_bnsum[t] / (float)NN;
    float var = g_bnsq[t] / (float)NN - mu * mu;
    g_mu[t] = mu;
    g_rstd[t] = rsqrtf(var + 1e-5f);
}

__global__ void k_bn_apply(const float* __restrict__ gam, const float* __restrict__ bet) {
    size_t i = (size_t)blockIdx.x * blockDim.x + threadIdx.x;
    if (i >= (size_t)NN * C1) return;
    int c = (int)(i & (C1 - 1));
    float v = eluf(g_agg[i]);
    g_feat[i] = (v - g_mu[c]) * g_rstd[c] * gam[c] + bet[c];
}

// ------------------------- final scorer -------------------------
__global__ void k_prep_final(const float* __restrict__ mlpW2, const float* __restrict__ mlpb2,
                             const float* __restrict__ fcW, const float* __restrict__ fcb) {
    int j = threadIdx.x;
    float s = 0.f;
    for (int k = 0; k < 64; k++) s += mlpW2[j * 64 + k] * fcW[128 + k];
    g_w2v[j] = s;
    if (j == 0) {
        float c = fcb[0];
        for (int k = 0; k < 64; k++) c += mlpb2[k] * fcW[128 + k];
        g_cb = c;
    }
}

__global__ void k_node_scalars(const float* __restrict__ fcW) {
    int w = (blockIdx.x * blockDim.x + threadIdx.x) >> 5;
    int lane = threadIdx.x & 31;
    if (w >= NN) return;
    const float* h = g_h3 + (size_t)w * 64;
    float v0 = h[lane], v1 = h[lane + 32];
    float a = v0 * fcW[lane] + v1 * fcW[lane + 32];
    float b = v0 * fcW[64 + lane] + v1 * fcW[96 + lane];
    for (int off = 16; off; off >>= 1) {
        a += __shfl_xor_sync(0xffffffffu, a, off);
        b += __shfl_xor_sync(0xffffffffu, b, off);
    }
    if (lane == 0) { g_hs[w] = a; g_hd[w] = b; }
}

// ------------------------- edge scorer: tf32 MMA edge-MLP, folded -------------------
#define OFF_MW 114688
__global__ __launch_bounds__(256) void k_edge_out(const int* __restrict__ ei,
                                                  const float* __restrict__ ea,
                                                  const float* __restrict__ mlpb1,
                                                  float* __restrict__ outp) {
    __shared__ float eas[128][17];
    __shared__ unsigned w1h[16][68];
    __shared__ unsigned w1l[16][68];
    __shared__ float b1s[64];
    __shared__ float w2vs[64];
    int t = threadIdx.x;
    int lane = t & 31;
    int wrp = t >> 5;
    int eBase = blockIdx.x * 128;

#pragma unroll
    for (int q = 0; q < 4; q++) {
        int idx = t + 256 * q;
        int k = idx >> 6, n = idx & 63;
        w1h[k][n] = g_whi[OFF_MW + idx];
        w1l[k][n] = g_wlo[OFF_MW + idx];
    }
    if (t < 64) { b1s[t] = mlpb1[t]; w2vs[t] = g_w2v[t]; }
#pragma unroll
    for (int q = 0; q < 2; q++) {
        int j = t + 256 * q;
        int row = j >> 2, kk = (j & 3) * 4;
        float4 v = *reinterpret_cast<const float4*>(ea + (size_t)(eBase + row) * 16 + kk);
        eas[row][kk] = v.x; eas[row][kk + 1] = v.y;
        eas[row][kk + 2] = v.z; eas[row][kk + 3] = v.w;
    }
    __syncthreads();

    int wr = wrp * 16;
    int ar = lane >> 2, ak = lane & 3;
    unsigned ahi[2][4], alo[2][4];
#pragma unroll
    for (int kf = 0; kf < 2; kf++) {
        split_tf32(eas[wr + ar][kf * 8 + ak],          ahi[kf][0], alo[kf][0]);
        split_tf32(eas[wr + ar + 8][kf * 8 + ak],      ahi[kf][1], alo[kf][1]);
        split_tf32(eas[wr + ar][kf * 8 + ak + 4],      ahi[kf][2], alo[kf][2]);
        split_tf32(eas[wr + ar + 8][kf * 8 + ak + 4],  ahi[kf][3], alo[kf][3]);
    }

    float dr0 = 0.f, dr1 = 0.f;
    int col0 = (lane & 3) * 2;
#pragma unroll
    for (int nt = 0; nt < 8; nt++) {
        float acc[4] = {0.f, 0.f, 0.f, 0.f};
        int bn = nt * 8 + (lane >> 2);
#pragma unroll
        for (int kf = 0; kf < 2; kf++) {
            int bk = kf * 8 + (lane & 3);
            unsigned bhi[2], blo[2];
            bhi[0] = w1h[bk][bn];     bhi[1] = w1h[bk + 4][bn];
            blo[0] = w1l[bk][bn];     blo[1] = w1l[bk + 4][bn];
            mma_tf32(acc, ahi[kf], bhi);
            mma_tf32(acc, alo[kf], bhi);
            mma_tf32(acc, ahi[kf], blo);
        }
        int c = nt * 8 + col0;
        float b0 = b1s[c], b1 = b1s[c + 1];
        float wv0 = w2vs[c], wv1 = w2vs[c + 1];
        dr0 += fmaxf(acc[0] + b0, 0.f) * wv0 + fmaxf(acc[1] + b1, 0.f) * wv1;
        dr1 += fmaxf(acc[2] + b0, 0.f) * wv0 + fmaxf(acc[3] + b1, 0.f) * wv1;
    }
    dr0 += __shfl_xor_sync(0xffffffffu, dr0, 1);
    dr0 += __shfl_xor_sync(0xffffffffu, dr0, 2);
    dr1 += __shfl_xor_sync(0xffffffffu, dr1, 1);
    dr1 += __shfl_xor_sync(0xffffffffu, dr1, 2);

    if ((lane & 3) == 0) {
        int r = lane >> 2;
        int e0 = eBase + wr + r;
        int e1 = e0 + 8;
        int s0 = ei[e0], d0 = ei[EE + e0];
        int s1 = ei[e1], d1 = ei[EE + e1];
        outp[e0] = g_hs[s0] + g_hd[d0] + dr0 + g_cb;
        outp[e1] = g_hs[s1] + g_hd[d1] + dr1 + g_cb;
    }
}

// ------------------------- launch -------------------------
static inline dim3 gemm_grid(int M, int Nc) { return dim3((Nc + 127) / 128, (M + 127) / 128); }

extern "C" void kernel_launch(void* const* d_in, const int* in_sizes, int n_in,
                              void* d_out, int out_size) {
    const float* x     = (const float*)d_in[0];
    const int*   ei    = (const int*)d_in[1];
    const float* ea    = (const float*)d_in[2];
    const float* W1    = (const float*)d_in[3];
    const float* a1s   = (const float*)d_in[4];
    const float* a1d   = (const float*)d_in[5];
    const float* b1    = (const float*)d_in[6];
    const float* W2    = (const float*)d_in[7];
    const float* a2s   = (const float*)d_in[8];
    const float* a2d   = (const float*)d_in[9];
    const float* b2    = (const float*)d_in[10];
    const float* W3    = (const float*)d_in[11];
    const float* a3s   = (const float*)d_in[12];
    const float* a3d   = (const float*)d_in[13];
    const float* b3    = (const float*)d_in[14];
    const float* bn1g  = (const float*)d_in[15];
    const float* bn1b  = (const float*)d_in[16];
    const float* bn2g  = (const float*)d_in[17];
    const float* bn2b  = (const float*)d_in[18];
    const float* mlpW1 = (const float*)d_in[19];
    const float* mlpb1 = (const float*)d_in[20];
    const float* mlpW2 = (const float*)d_in[21];
    const float* mlpb2 = (const float*)d_in[22];
    const float* fcW   = (const float*)d_in[23];
    const float* fcb   = (const float*)d_in[24];
    float* outp = (float*)d_out;

    static bool attrs_set = false;
    if (!attrs_set) {
        cudaFuncSetAttribute(k_gemm_tf32<0>, cudaFuncAttributeMaxDynamicSharedMemorySize, GEMM_SMEM);
        cudaFuncSetAttribute(k_gemm_tf32<1>, cudaFuncAttributeMaxDynamicSharedMemorySize, GEMM_SMEM);
        attrs_set = true;
    }

    const int OFF_W1 = 0, OFF_W2 = 32768, OFF_W3 = 98304;

    // launches 0..2
    k_init<<<196, 256>>>();
    k_hist<<<(EE + 255) / 256, 256>>>(ei);
    k_wsplit<<<(32768 + 255) / 256, 256>>>(W1, 32768, OFF_W1);
    // launch #3 (profiled by ncu): layer-1 GEMM (fused ls/ld epilogue)
    k_gemm_tf32<0><<<gemm_grid(NN, C1), 256, GEMM_SMEM>>>(x, a1s, a1d, OFF_W1, NN, 128, C1, 4);

    k_wsplit<<<(65536 + 255) / 256, 256>>>(W2, 65536, OFF_W2);
    k_wsplit<<<(16384 + 255) / 256, 256>>>(W3, 16384, OFF_W3);
    k_wsplit<<<4, 256>>>(mlpW1, 1024, OFF_MW);

    k_scan1<<<196, 256>>>();
    k_scan2<<<1, 256>>>();
    k_scan3<<<(NN + 255) / 256, 256>>>();
    k_scatter<<<(ETOT + 255) / 256, 256>>>(ei);

    const int aggBlocks = (NN * 32 + 255) / 256;
    const int bnApplyBlocks = (int)(((size_t)NN * C1 + 255) / 256);

    // ---- layer 1 (GEMM already issued)
    k_aggregate<4, 0><<<aggBlocks, 256>>>(b1);
    k_zero2<<<196, 256>>>();                       // clears ls/ld + bn accumulators
    k_bn_stats<<<512, C1>>>();
    k_bn_finalize<<<1, C1>>>();
    k_bn_apply<<<bnApplyBlocks, 256>>>(bn1g, bn1b);

    // ---- layer 2
    k_gemm_tf32<1><<<gemm_grid(NN, C1), 256, GEMM_SMEM>>>(nullptr, a2s, a2d, OFF_W2, NN, C1, C1, 4);
    k_aggregate<4, 0><<<aggBlocks, 256>>>(b2);
    k_zero2<<<196, 256>>>();
    k_bn_stats<<<512, C1>>>();
    k_bn_finalize<<<1, C1>>>();
    k_bn_apply<<<bnApplyBlocks, 256>>>(bn2g, bn2b);

    // ---- layer 3
    k_gemm_tf32<1><<<gemm_grid(NN, HIDV), 256, GEMM_SMEM>>>(nullptr, a3s, a3d, OFF_W3, NN, C1, HIDV, 1);
    k_aggregate<1, 1><<<aggBlocks, 256>>>(b3);

    // ---- final scorer
    k_prep_final<<<1, 64>>>(mlpW2, mlpb2, fcW, fcb);
    k_node_scalars<<<(NN * 32 + 255) / 256, 256>>>(fcW);
    k_edge_out<<<12500, 256>>>(ei, ea, mlpb1, outp);

    (void)in_sizes; (void)n_in; (void)out_size;
}

// round 9
// speedup vs baseline: 1.6331x; 1.0874x over previous
#include <cuda_runtime.h>
#include <cuda_fp16.h>
#include <cuda_bf16.h>

#define NN 50000
#define EE 1600000
#define ETOT (EE + NN)
#define C1 256
#define HIDV 64
#define SLOPE 0.2f

// ------------------------- scratch (static device globals) -------------------------
__device__ __align__(16) __half g_hwh[(size_t)NN * C1];    // GEMM output fp16 (gather)
__device__ __align__(16) float  g_feat[(size_t)NN * C1];   // post-BN features
__device__ __align__(16) float  g_agg[(size_t)NN * C1];    // attention aggregate
__device__ __align__(16) float  g_h3[(size_t)NN * HIDV];   // layer-3 output
__device__ __align__(16) float  g_ls[NN * 4];
__device__ __align__(16) float  g_ld[NN * 4];
__device__ int   g_deg[NN];
__device__ int   g_off[NN + 1];
__device__ int   g_cur[NN];
__device__ int   g_csr[ETOT];
__device__ int   g_bsum[256];
__device__ float g_bnsum[C1];
__device__ float g_bnsq[C1];
__device__ float g_mu[C1];
__device__ float g_rstd[C1];
__device__ float g_w2v[HIDV];
__device__ float g_cb;
__device__ float g_hs[NN];
__device__ float g_hd[NN];
// packed bf16x2 hi/lo GEMM weights (k-pair major): W1@0(16384) W2@16384(32768) W3@49152(8192)
__device__ __align__(16) unsigned g_wbh[57344];
__device__ __align__(16) unsigned g_wbl[57344];
// tf32 hi/lo for edge-MLP W1 only
__device__ __align__(16) unsigned g_whi[1024];
__device__ __align__(16) unsigned g_wlo[1024];

// ------------------------- split helpers -------------------------
__device__ __forceinline__ void split_tf32(float x, unsigned& hi, unsigned& lo) {
    unsigned h;
    asm("cvt.rna.tf32.f32 %0, %1;" : "=r"(h) : "f"(x));
    float l = x - __uint_as_float(h);
    unsigned lb;
    asm("cvt.rna.tf32.f32 %0, %1;" : "=r"(lb) : "f"(l));
    hi = h; lo = lb;
}

__device__ __forceinline__ void split2_bf16(float x0, float x1, unsigned& hw, unsigned& lw) {
    __nv_bfloat16 h0 = __float2bfloat16_rn(x0);
    __nv_bfloat16 h1 = __float2bfloat16_rn(x1);
    __nv_bfloat16 l0 = __float2bfloat16_rn(x0 - __bfloat162float(h0));
    __nv_bfloat16 l1 = __float2bfloat16_rn(x1 - __bfloat162float(h1));
    hw = ((unsigned)__bfloat16_as_ushort(h1) << 16) | (unsigned)__bfloat16_as_ushort(h0);
    lw = ((unsigned)__bfloat16_as_ushort(l1) << 16) | (unsigned)__bfloat16_as_ushort(l0);
}

__device__ __forceinline__ void mma_bf16(float* c, const unsigned* a, const unsigned* b) {
    asm volatile("mma.sync.aligned.m16n8k16.row.col.f32.bf16.bf16.f32 "
                 "{%0,%1,%2,%3}, {%4,%5,%6,%7}, {%8,%9}, {%0,%1,%2,%3};"
                 : "+f"(c[0]), "+f"(c[1]), "+f"(c[2]), "+f"(c[3])
                 : "r"(a[0]), "r"(a[1]), "r"(a[2]), "r"(a[3]),
                   "r"(b[0]), "r"(b[1]));
}

__device__ __forceinline__ void mma_tf32(float* c, const unsigned* a, const unsigned* b) {
    asm volatile("mma.sync.aligned.m16n8k8.row.col.f32.tf32.tf32.f32 "
                 "{%0,%1,%2,%3}, {%4,%5,%6,%7}, {%8,%9}, {%0,%1,%2,%3};"
                 : "+f"(c[0]), "+f"(c[1]), "+f"(c[2]), "+f"(c[3])
                 : "r"(a[0]), "r"(a[1]), "r"(a[2]), "r"(a[3]),
                   "r"(b[0]), "r"(b[1]));
}

// ------------------------- weight pre-split kernels -------------------------
// packed bf16x2 k-pair-major: word(kp, n) = {W[2kp][n], W[2kp+1][n]}
__global__ void k_wsplit_pk(const float* __restrict__ W, int Kd, int Nc, int offset) {
    int i = blockIdx.x * blockDim.x + threadIdx.x;
    int total = (Kd >> 1) * Nc;
    if (i >= total) return;
    int kp = i / Nc, n = i - kp * Nc;
    float x0 = W[(size_t)(2 * kp) * Nc + n];
    float x1 = W[(size_t)(2 * kp + 1) * Nc + n];
    unsigned hw, lw;
    split2_bf16(x0, x1, hw, lw);
    g_wbh[offset + i] = hw;
    g_wbl[offset + i] = lw;
}

__global__ void k_wsplit(const float* __restrict__ W, int count, int offset) {
    int i = blockIdx.x * blockDim.x + threadIdx.x;
    if (i < count) {
        unsigned h, l;
        split_tf32(W[i], h, l);
        g_whi[offset + i] = h;
        g_wlo[offset + i] = l;
    }
}

// ------------------------- init / zero kernels -------------------------
__global__ void k_init() {
    int i = blockIdx.x * blockDim.x + threadIdx.x;
    if (i < NN) g_deg[i] = 1;
    for (int j = i; j < NN * 4; j += 50176) { g_ls[j] = 0.f; g_ld[j] = 0.f; }
    if (i < C1) { g_bnsum[i] = 0.f; g_bnsq[i] = 0.f; }
}

__global__ void k_zero2() {
    int i = blockIdx.x * blockDim.x + threadIdx.x;
    for (int j = i; j < NN * 4; j += 50176) { g_ls[j] = 0.f; g_ld[j] = 0.f; }
    if (i < C1) { g_bnsum[i] = 0.f; g_bnsq[i] = 0.f; }
}

// ------------------------- CSR build -------------------------
__global__ void k_hist(const int* __restrict__ ei) {
    int e = blockIdx.x * blockDim.x + threadIdx.x;
    if (e < EE) atomicAdd(&g_deg[ei[EE + e]], 1);
}

__global__ void k_scan1() {
    __shared__ int sh[256];
    int t = threadIdx.x;
    int i = blockIdx.x * 256 + t;
    int v = (i < NN) ? g_deg[i] : 0;
    sh[t] = v;
    __syncthreads();
#pragma unroll
    for (int st = 1; st < 256; st <<= 1) {
        int a = (t >= st) ? sh[t - st] : 0;
        __syncthreads();
        sh[t] += a;
        __syncthreads();
    }
    if (i < NN) g_off[i] = sh[t] - v;
    if (t == 255) g_bsum[blockIdx.x] = sh[255];
}

__global__ void k_scan2() {
    __shared__ int sh[256];
    int t = threadIdx.x;
    int v = (t < 196) ? g_bsum[t] : 0;
    sh[t] = v;
    __syncthreads();
#pragma unroll
    for (int st = 1; st < 256; st <<= 1) {
        int a = (t >= st) ? sh[t - st] : 0;
        __syncthreads();
        sh[t] += a;
        __syncthreads();
    }
    g_bsum[t] = sh[t] - v;
    if (t == 255) g_off[NN] = sh[255];
}

__global__ void k_scan3() {
    int i = blockIdx.x * blockDim.x + threadIdx.x;
    if (i < NN) {
        int o = g_off[i] + g_bsum[i >> 8];
        g_off[i] = o;
        g_cur[i] = o;
    }
}

__global__ void k_scatter(const int* __restrict__ ei) {
    int e = blockIdx.x * blockDim.x + threadIdx.x;
    if (e >= ETOT) return;
    int s, d;
    if (e < EE) { s = ei[e]; d = ei[EE + e]; }
    else        { s = e - EE; d = e - EE; }
    int pos = atomicAdd(&g_cur[d], 1);
    g_csr[pos] = s;
}

// ------------------------- BF16 split GEMM: 2-stage cp.async, chunk K=32 --------------
// smem per stage: Ah 128x20 words (10240B) | Al (10240B) | Bh 16x132 (8448B) | Bl (8448B)
#define A_STR 20
#define B_STR 132
#define O_AL  10240
#define O_BH  20480
#define O_BL  28928
#define ST_SZ 37376
#define GEMM_SMEM (2 * ST_SZ)

template <int A_SRC>
__global__ __launch_bounds__(256, 2) void k_gemm_bf16(const float* __restrict__ Aparam,
                                                      const float* __restrict__ asv,
                                                      const float* __restrict__ adv,
                                                      int boff, int M, int K, int Nc, int H) {
    const float* A = (A_SRC == 0) ? Aparam : (const float*)g_feat;
    extern __shared__ char smx[];
    unsigned smBase = (unsigned)__cvta_generic_to_shared(smx);

    int t = threadIdx.x;
    int lane = t & 31;
    int wid = t >> 5;
    int warpM = (wid & 3) * 32;
    int warpN = (wid >> 2) * 64;
    int rowBase = blockIdx.y * 128;
    int colBase = blockIdx.x * 128;

    // staging indices: A tile 128x32 floats = 1024 float4; j = t+256q: row=j>>3, kf=j&7
    int aRow = t >> 3, aKf = t & 7;
    // B tile 16 k-pairs x 128 words; q loop: kk = t>>5 + 8q, c4 = (t&31)*4
    int bK = t >> 5, bC = (t & 31) * 4;

    float acc[2][8][4];
#pragma unroll
    for (int mt = 0; mt < 2; mt++)
#pragma unroll
        for (int nt = 0; nt < 8; nt++)
#pragma unroll
            for (int r = 0; r < 4; r++) acc[mt][nt][r] = 0.f;

    int nCh = K >> 5;
    float4 va[4];

    auto loadA = [&](int k0) {
#pragma unroll
        for (int q = 0; q < 4; q++) {
            int gr = rowBase + aRow + 32 * q;
            va[q] = make_float4(0.f, 0.f, 0.f, 0.f);
            if (gr < M)
                va[q] = *reinterpret_cast<const float4*>(A + (size_t)gr * K + k0 + aKf * 4);
        }
    };
    auto stsA = [&](int stg) {
        unsigned* Ah = reinterpret_cast<unsigned*>(smx + stg * ST_SZ);
        unsigned* Al = reinterpret_cast<unsigned*>(smx + stg * ST_SZ + O_AL);
#pragma unroll
        for (int q = 0; q < 4; q++) {
            int row = aRow + 32 * q;
            unsigned h01, l01, h23, l23;
            split2_bf16(va[q].x, va[q].y, h01, l01);
            split2_bf16(va[q].z, va[q].w, h23, l23);
            int base = row * A_STR + aKf * 2;
            Ah[base] = h01; Ah[base + 1] = h23;
            Al[base] = l01; Al[base + 1] = l23;
        }
    };
    auto cpB = [&](int k0, int stg) {
        int kp0 = k0 >> 1;
#pragma unroll
        for (int q = 0; q < 2; q++) {
            int kk = bK + 8 * q;
            int gc = colBase + bC;
            int vbytes = (gc + 3 < Nc) ? 16 : 0;
            size_t idx = (size_t)boff + (size_t)(kp0 + kk) * Nc + (vbytes ? gc : 0);
            unsigned dH = smBase + stg * ST_SZ + O_BH + (kk * B_STR + bC) * 4;
            unsigned dL = smBase + stg * ST_SZ + O_BL + (kk * B_STR + bC) * 4;
            asm volatile("cp.async.cg.shared.global [%0], [%1], 16, %2;"
                         :: "r"(dH), "l"(g_wbh + idx), "r"(vbytes));
            asm volatile("cp.async.cg.shared.global [%0], [%1], 16, %2;"
                         :: "r"(dL), "l"(g_wbl + idx), "r"(vbytes));
        }
    };

    // prologue
    loadA(0);
    cpB(0, 0);
    asm volatile("cp.async.commit_group;" ::: "memory");
    stsA(0);

    int buf = 0;
    for (int c = 0; c < nCh; c++) {
        asm volatile("cp.async.wait_group 0;" ::: "memory");
        __syncthreads();
        if (c + 1 < nCh) {
            loadA((c + 1) * 32);
            cpB((c + 1) * 32, buf ^ 1);
            asm volatile("cp.async.commit_group;" ::: "memory");
        }
        {
            unsigned* Ah = reinterpret_cast<unsigned*>(smx + buf * ST_SZ);
            unsigned* Al = reinterpret_cast<unsigned*>(smx + buf * ST_SZ + O_AL);
            unsigned* Bh = reinterpret_cast<unsigned*>(smx + buf * ST_SZ + O_BH);
            unsigned* Bl = reinterpret_cast<unsigned*>(smx + buf * ST_SZ + O_BL);
            int kq = lane & 3;
            int arow = warpM + (lane >> 2);
#pragma unroll
            for (int s = 0; s < 2; s++) {
                unsigned ahi[2][4], alo[2][4];
#pragma unroll
                for (int mt = 0; mt < 2; mt++) {
                    int r0 = (arow + mt * 16) * A_STR + s * 8;
                    int r1 = r0 + 8 * A_STR;
                    ahi[mt][0] = Ah[r0 + kq];     alo[mt][0] = Al[r0 + kq];
                    ahi[mt][1] = Ah[r1 + kq];     alo[mt][1] = Al[r1 + kq];
                    ahi[mt][2] = Ah[r0 + kq + 4]; alo[mt][2] = Al[r0 + kq + 4];
                    ahi[mt][3] = Ah[r1 + kq + 4]; alo[mt][3] = Al[r1 + kq + 4];
                }
#pragma unroll
                for (int nt = 0; nt < 8; nt++) {
                    int bn = warpN + nt * 8 + (lane >> 2);
                    unsigned bhi[2], blo[2];
                    bhi[0] = Bh[(s * 8 + kq) * B_STR + bn];
                    bhi[1] = Bh[(s * 8 + kq + 4) * B_STR + bn];
                    blo[0] = Bl[(s * 8 + kq) * B_STR + bn];
                    blo[1] = Bl[(s * 8 + kq + 4) * B_STR + bn];
#pragma unroll
                    for (int mt = 0; mt < 2; mt++) {
                        mma_bf16(acc[mt][nt], ahi[mt], bhi);
                        mma_bf16(acc[mt][nt], alo[mt], bhi);
                        mma_bf16(acc[mt][nt], ahi[mt], blo);
                    }
                }
            }
        }
        if (c + 1 < nCh) stsA(buf ^ 1);
        buf ^= 1;
    }

    // epilogue: fp16 store + fused ls/ld
#pragma unroll
    for (int mt = 0; mt < 2; mt++) {
#pragma unroll
        for (int nt = 0; nt < 8; nt++) {
            int row0 = rowBase + warpM + mt * 16 + (lane >> 2);
            int col0 = colBase + warpN + nt * 8 + (lane & 3) * 2;
            if (col0 < Nc) {
                if (row0 < M)
                    *reinterpret_cast<__half2*>(g_hwh + (size_t)row0 * Nc + col0) =
                        __floats2half2_rn(acc[mt][nt][0], acc[mt][nt][1]);
                if (row0 + 8 < M)
                    *reinterpret_cast<__half2*>(g_hwh + (size_t)(row0 + 8) * Nc + col0) =
                        __floats2half2_rn(acc[mt][nt][2], acc[mt][nt][3]);
            }
        }
    }

    if (warpN < Nc) {
        int head = (colBase + warpN) >> 6;
        float pls[2][2] = {{0.f, 0.f}, {0.f, 0.f}};
        float pld[2][2] = {{0.f, 0.f}, {0.f, 0.f}};
#pragma unroll
        for (int nt = 0; nt < 8; nt++) {
            int c0 = colBase + warpN + nt * 8 + (lane & 3) * 2;
            float2 ws = *reinterpret_cast<const float2*>(asv + c0);
            float2 wd = *reinterpret_cast<const float2*>(adv + c0);
#pragma unroll
            for (int mt = 0; mt < 2; mt++) {
                pls[mt][0] += acc[mt][nt][0] * ws.x + acc[mt][nt][1] * ws.y;
                pls[mt][1] += acc[mt][nt][2] * ws.x + acc[mt][nt][3] * ws.y;
                pld[mt][0] += acc[mt][nt][0] * wd.x + acc[mt][nt][1] * wd.y;
                pld[mt][1] += acc[mt][nt][2] * wd.x + acc[mt][nt][3] * wd.y;
            }
        }
#pragma unroll
        for (int mt = 0; mt < 2; mt++)
#pragma unroll
            for (int rr = 0; rr < 2; rr++) {
                pls[mt][rr] += __shfl_xor_sync(0xffffffffu, pls[mt][rr], 1);
                pls[mt][rr] += __shfl_xor_sync(0xffffffffu, pls[mt][rr], 2);
                pld[mt][rr] += __shfl_xor_sync(0xffffffffu, pld[mt][rr], 1);
                pld[mt][rr] += __shfl_xor_sync(0xffffffffu, pld[mt][rr], 2);
            }
        if ((lane & 3) == 0) {
#pragma unroll
            for (int mt = 0; mt < 2; mt++)
#pragma unroll
                for (int rr = 0; rr < 2; rr++) {
                    int row = rowBase + warpM + mt * 16 + (lane >> 2) + rr * 8;
                    if (row < M) {
                        atomicAdd(&g_ls[row * H + head], pls[mt][rr]);
                        atomicAdd(&g_ld[row * H + head], pld[mt][rr]);
                    }
                }
        }
    }
}

// ------------------------- GAT aggregate: warp/dst, fp16 gather, idx prefetch ---------
template <int H, int DSTSEL>
__global__ void k_aggregate(const float* __restrict__ bias) {
    float* out = (DSTSEL == 0) ? (float*)g_agg : (float*)g_h3;
    int w = (blockIdx.x * blockDim.x + threadIdx.x) >> 5;
    int lane = threadIdx.x & 31;
    if (w >= NN) return;
    int beg = g_off[w], end = g_off[w + 1];

    if (H == 4) {
        float4 ldv = *reinterpret_cast<const float4*>(g_ld + w * 4);
        float s0 = 0.f, s1 = 0.f, s2 = 0.f, s3 = 0.f;
        float a0 = 0.f, a1 = 0.f, a2 = 0.f, a3 = 0.f;
        float a4 = 0.f, a5 = 0.f, a6 = 0.f, a7 = 0.f;
        int hd = lane >> 3;
        int sCur = g_csr[beg];
        for (int i = beg; i < end; i++) {
            int s = sCur;
            if (i + 1 < end) sCur = g_csr[i + 1];
            float4 lsv = *reinterpret_cast<const float4*>(g_ls + s * 4);
            float l0 = lsv.x + ldv.x; l0 = l0 > 0.f ? l0 : SLOPE * l0;
            float l1 = lsv.y + ldv.y; l1 = l1 > 0.f ? l1 : SLOPE * l1;
            float l2 = lsv.z + ldv.z; l2 = l2 > 0.f ? l2 : SLOPE * l2;
            float l3 = lsv.w + ldv.w; l3 = l3 > 0.f ? l3 : SLOPE * l3;
            float p0 = __expf(l0), p1 = __expf(l1), p2 = __expf(l2), p3 = __expf(l3);
            s0 += p0; s1 += p1; s2 += p2; s3 += p3;
            float p = (hd == 0) ? p0 : (hd == 1) ? p1 : (hd == 2) ? p2 : p3;
            uint4 v = reinterpret_cast<const uint4*>(g_hwh + (size_t)s * 256)[lane];
            float2 f0 = __half22float2(*reinterpret_cast<__half2*>(&v.x));
            float2 f1 = __half22float2(*reinterpret_cast<__half2*>(&v.y));
            float2 f2 = __half22float2(*reinterpret_cast<__half2*>(&v.z));
            float2 f3 = __half22float2(*reinterpret_cast<__half2*>(&v.w));
            a0 += p * f0.x; a1 += p * f0.y; a2 += p * f1.x; a3 += p * f1.y;
            a4 += p * f2.x; a5 += p * f2.y; a6 += p * f3.x; a7 += p * f3.y;
        }
        float ss = (hd == 0) ? s0 : (hd == 1) ? s1 : (hd == 2) ? s2 : s3;
        float inv = 1.f / (ss + 1e-16f);
        const float* bp = bias + lane * 8;
        float4 bv0 = *reinterpret_cast<const float4*>(bp);
        float4 bv1 = *reinterpret_cast<const float4*>(bp + 4);
        float* op = out + (size_t)w * 256 + lane * 8;
        *reinterpret_cast<float4*>(op) =
            make_float4(a0 * inv + bv0.x, a1 * inv + bv0.y, a2 * inv + bv0.z, a3 * inv + bv0.w);
        *reinterpret_cast<float4*>(op + 4) =
            make_float4(a4 * inv + bv1.x, a5 * inv + bv1.y, a6 * inv + bv1.z, a7 * inv + bv1.w);
    } else {
        float ldh = g_ld[w];
        float ssum = 0.f;
        float ax = 0.f, ay = 0.f;
        int sCur = g_csr[beg];
        for (int i = beg; i < end; i++) {
            int s = sCur;
            if (i + 1 < end) sCur = g_csr[i + 1];
            float lg = g_ls[s] + ldh;
            lg = lg > 0.f ? lg : SLOPE * lg;
            float p = __expf(lg);
            ssum += p;
            __half2 hv = reinterpret_cast<const __half2*>(g_hwh + (size_t)s * 64)[lane];
            float2 v = __half22float2(hv);
            ax += p * v.x; ay += p * v.y;
        }
        float inv = 1.f / (ssum + 1e-16f);
        float2 b = reinterpret_cast<const float2*>(bias)[lane];
        reinterpret_cast<float2*>(out + (size_t)w * 64)[lane] =
            make_float2(ax * inv + b.x, ay * inv + b.y);
    }
}

// ------------------------- ELU + BatchNorm -------------------------
__device__ __forceinline__ float eluf(float x) { return x > 0.f ? x : expm1f(x); }

__global__ void k_bn_stats() {
    int t = threadIdx.x;
    float s = 0.f, s2 = 0.f;
    for (int r = blockIdx.x; r < NN; r += gridDim.x) {
        float v = eluf(g_agg[(size_t)r * C1 + t]);
        s += v;
        s2 += v * v;
    }
    atomicAdd(&g_bnsum[t], s);
    atomicAdd(&g_bnsq[t], s2);
}

__global__ void k_bn_finalize() {
    int t = threadIdx.x;
    float mu = g_bnsum[t] / (float)NN;
    float var = g_bnsq[t] / (float)NN - mu * mu;
    g_mu[t] = mu;
    g_rstd[t] = rsqrtf(var + 1e-5f);
}

__global__ void k_bn_apply(const float* __restrict__ gam, const float* __restrict__ bet) {
    size_t i = (size_t)blockIdx.x * blockDim.x + threadIdx.x;
    if (i >= (size_t)NN * C1) return;
    int c = (int)(i & (C1 - 1));
    float v = eluf(g_agg[i]);
    g_feat[i] = (v - g_mu[c]) * g_rstd[c] * gam[c] + bet[c];
}

// ------------------------- final scorer -------------------------
__global__ void k_prep_final(const float* __restrict__ mlpW2, const float* __restrict__ mlpb2,
                             const float* __restrict__ fcW, const float* __restrict__ fcb) {
    int j = threadIdx.x;
    float s = 0.f;
    for (int k = 0; k < 64; k++) s += mlpW2[j * 64 + k] * fcW[128 + k];
    g_w2v[j] = s;
    if (j == 0) {
        float c = fcb[0];
        for (int k = 0; k < 64; k++) c += mlpb2[k] * fcW[128 + k];
        g_cb = c;
    }
}

__global__ void k_node_scalars(const float* __restrict__ fcW) {
    int w = (blockIdx.x * blockDim.x + threadIdx.x) >> 5;
    int lane = threadIdx.x & 31;
    if (w >= NN) return;
    const float* h = g_h3 + (size_t)w * 64;
    float v0 = h[lane], v1 = h[lane + 32];
    float a = v0 * fcW[lane] + v1 * fcW[lane + 32];
    float b = v0 * fcW[64 + lane] + v1 * fcW[96 + lane];
    for (int off = 16; off; off >>= 1) {
        a += __shfl_xor_sync(0xffffffffu, a, off);
        b += __shfl_xor_sync(0xffffffffu, b, off);
    }
    if (lane == 0) { g_hs[w] = a; g_hd[w] = b; }
}

// ------------------------- edge scorer: tf32 MMA edge-MLP, folded -------------------
__global__ __launch_bounds__(256) void k_edge_out(const int* __restrict__ ei,
                                                  const float* __restrict__ ea,
                                                  const float* __restrict__ mlpb1,
                                                  float* __restrict__ outp) {
    __shared__ float eas[128][17];
    __shared__ unsigned w1h[16][68];
    __shared__ unsigned w1l[16][68];
    __shared__ float b1s[64];
    __shared__ float w2vs[64];
    int t = threadIdx.x;
    int lane = t & 31;
    int wrp = t >> 5;
    int eBase = blockIdx.x * 128;

#pragma unroll
    for (int q = 0; q < 4; q++) {
        int idx = t + 256 * q;
        int k = idx >> 6, n = idx & 63;
        w1h[k][n] = g_whi[idx];
        w1l[k][n] = g_wlo[idx];
    }
    if (t < 64) { b1s[t] = mlpb1[t]; w2vs[t] = g_w2v[t]; }
#pragma unroll
    for (int q = 0; q < 2; q++) {
        int j = t + 256 * q;
        int row = j >> 2, kk = (j & 3) * 4;
        float4 v = *reinterpret_cast<const float4*>(ea + (size_t)(eBase + row) * 16 + kk);
        eas[row][kk] = v.x; eas[row][kk + 1] = v.y;
        eas[row][kk + 2] = v.z; eas[row][kk + 3] = v.w;
    }
    __syncthreads();

    int wr = wrp * 16;
    int ar = lane >> 2, ak = lane & 3;
    unsigned ahi[2][4], alo[2][4];
#pragma unroll
    for (int kf = 0; kf < 2; kf++) {
        split_tf32(eas[wr + ar][kf * 8 + ak],          ahi[kf][0], alo[kf][0]);
        split_tf32(eas[wr + ar + 8][kf * 8 + ak],      ahi[kf][1], alo[kf][1]);
        split_tf32(eas[wr + ar][kf * 8 + ak + 4],      ahi[kf][2], alo[kf][2]);
        split_tf32(eas[wr + ar + 8][kf * 8 + ak + 4],  ahi[kf][3], alo[kf][3]);
    }

    float dr0 = 0.f, dr1 = 0.f;
    int col0 = (lane & 3) * 2;
#pragma unroll
    for (int nt = 0; nt < 8; nt++) {
        float acc[4] = {0.f, 0.f, 0.f, 0.f};
        int bn = nt * 8 + (lane >> 2);
#pragma unroll
        for (int kf = 0; kf < 2; kf++) {
            int bk = kf * 8 + (lane & 3);
            unsigned bhi[2], blo[2];
            bhi[0] = w1h[bk][bn];     bhi[1] = w1h[bk + 4][bn];
            blo[0] = w1l[bk][bn];     blo[1] = w1l[bk + 4][bn];
            mma_tf32(acc, ahi[kf], bhi);
            mma_tf32(acc, alo[kf], bhi);
            mma_tf32(acc, ahi[kf], blo);
        }
        int c = nt * 8 + col0;
        float b0 = b1s[c], b1 = b1s[c + 1];
        float wv0 = w2vs[c], wv1 = w2vs[c + 1];
        dr0 += fmaxf(acc[0] + b0, 0.f) * wv0 + fmaxf(acc[1] + b1, 0.f) * wv1;
        dr1 += fmaxf(acc[2] + b0, 0.f) * wv0 + fmaxf(acc[3] + b1, 0.f) * wv1;
    }
    dr0 += __shfl_xor_sync(0xffffffffu, dr0, 1);
    dr0 += __shfl_xor_sync(0xffffffffu, dr0, 2);
    dr1 += __shfl_xor_sync(0xffffffffu, dr1, 1);
    dr1 += __shfl_xor_sync(0xffffffffu, dr1, 2);

    if ((lane & 3) == 0) {
        int r = lane >> 2;
        int e0 = eBase + wr + r;
        int e1 = e0 + 8;
        int s0 = ei[e0], d0 = ei[EE + e0];
        int s1 = ei[e1], d1 = ei[EE + e1];
        outp[e0] = g_hs[s0] + g_hd[d0] + dr0 + g_cb;
        outp[e1] = g_hs[s1] + g_hd[d1] + dr1 + g_cb;
    }
}

// ------------------------- launch -------------------------
static inline dim3 gemm_grid(int M, int Nc) { return dim3((Nc + 127) / 128, (M + 127) / 128); }

extern "C" void kernel_launch(void* const* d_in, const int* in_sizes, int n_in,
                              void* d_out, int out_size) {
    const float* x     = (const float*)d_in[0];
    const int*   ei    = (const int*)d_in[1];
    const float* ea    = (const float*)d_in[2];
    const float* W1    = (const float*)d_in[3];
    const float* a1s   = (const float*)d_in[4];
    const float* a1d   = (const float*)d_in[5];
    const float* b1    = (const float*)d_in[6];
    const float* W2    = (const float*)d_in[7];
    const float* a2s   = (const float*)d_in[8];
    const float* a2d   = (const float*)d_in[9];
    const float* b2    = (const float*)d_in[10];
    const float* W3    = (const float*)d_in[11];
    const float* a3s   = (const float*)d_in[12];
    const float* a3d   = (const float*)d_in[13];
    const float* b3    = (const float*)d_in[14];
    const float* bn1g  = (const float*)d_in[15];
    const float* bn1b  = (const float*)d_in[16];
    const float* bn2g  = (const float*)d_in[17];
    const float* bn2b  = (const float*)d_in[18];
    const float* mlpW1 = (const float*)d_in[19];
    const float* mlpb1 = (const float*)d_in[20];
    const float* mlpW2 = (const float*)d_in[21];
    const float* mlpb2 = (const float*)d_in[22];
    const float* fcW   = (const float*)d_in[23];
    const float* fcb   = (const float*)d_in[24];
    float* outp = (float*)d_out;

    static bool attrs_set = false;
    if (!attrs_set) {
        cudaFuncSetAttribute(k_gemm_bf16<0>, cudaFuncAttributeMaxDynamicSharedMemorySize, GEMM_SMEM);
        cudaFuncSetAttribute(k_gemm_bf16<1>, cudaFuncAttributeMaxDynamicSharedMemorySize, GEMM_SMEM);
        attrs_set = true;
    }

    const int PW1 = 0, PW2 = 16384, PW3 = 49152;

    // launches 0..2
    k_init<<<196, 256>>>();
    k_hist<<<(EE + 255) / 256, 256>>>(ei);
    k_wsplit_pk<<<(16384 + 255) / 256, 256>>>(W1, 128, 256, PW1);
    // launch #3 (profiled): layer-1 GEMM
    k_gemm_bf16<0><<<gemm_grid(NN, C1), 256, GEMM_SMEM>>>(x, a1s, a1d, PW1, NN, 128, C1, 4);

    k_wsplit_pk<<<(32768 + 255) / 256, 256>>>(W2, 256, 256, PW2);
    k_wsplit_pk<<<(8192 + 255) / 256, 256>>>(W3, 256, 64, PW3);
    k_wsplit<<<4, 256>>>(mlpW1, 1024, 0);

    k_scan1<<<196, 256>>>();
    k_scan2<<<1, 256>>>();
    k_scan3<<<(NN + 255) / 256, 256>>>();
    k_scatter<<<(ETOT + 255) / 256, 256>>>(ei);

    const int aggBlocks = (NN * 32 + 255) / 256;
    const int bnApplyBlocks = (int)(((size_t)NN * C1 + 255) / 256);

    // ---- layer 1 (GEMM already issued)
    k_aggregate<4, 0><<<aggBlocks, 256>>>(b1);
    k_zero2<<<196, 256>>>();
    k_bn_stats<<<512, C1>>>();
    k_bn_finalize<<<1, C1>>>();
    k_bn_apply<<<bnApplyBlocks, 256>>>(bn1g, bn1b);

    // ---- layer 2
    k_gemm_bf16<1><<<gemm_grid(NN, C1), 256, GEMM_SMEM>>>(nullptr, a2s, a2d, PW2, NN, C1, C1, 4);
    k_aggregate<4, 0><<<aggBlocks, 256>>>(b2);
    k_zero2<<<196, 256>>>();
    k_bn_stats<<<512, C1>>>();
    k_bn_finalize<<<1, C1>>>();
    k_bn_apply<<<bnApplyBlocks, 256>>>(bn2g, bn2b);

    // ---- layer 3
    k_gemm_bf16<1><<<gemm_grid(NN, HIDV), 256, GEMM_SMEM>>>(nullptr, a3s, a3d, PW3, NN, C1, HIDV, 1);
    k_aggregate<1, 1><<<aggBlocks, 256>>>(b3);

    // ---- final scorer
    k_prep_final<<<1, 64>>>(mlpW2, mlpb2, fcW, fcb);
    k_node_scalars<<<(NN * 32 + 255) / 256, 256>>>(fcW);
    k_edge_out<<<12500, 256>>>(ei, ea, mlpb1, outp);

    (void)in_sizes; (void)n_in; (void)out_size;
}